// round 9
// baseline (speedup 1.0000x reference)
#include <cuda_runtime.h>
#include <cuda_fp16.h>
#include <cstdint>

// Problem constants
#define BATCH 16
#define CCH   512
#define NPIX  4096          // 64*64
#define NHEAD 8
#define HDIM  64
#define EPS   1e-6f

// Tensor-core GEMM tile config
#define BMT 128
#define BNT 128
#define BKT 32

// Scratch (device globals - no allocation at launch time).
__device__ float g_QK[(size_t)BATCH * 1024 * NPIX];   // relu(w_qk @ (x+pos)): q = ch 0..511, k = ch 512..1023
__device__ float g_V [(size_t)BATCH * CCH  * NPIX];   // V, then attention output (reused)
__device__ float g_KV[(size_t)BATCH * NHEAD * 65 * 64];

// ---------------------------------------------------------------------------
// helpers
// ---------------------------------------------------------------------------
__device__ __forceinline__ uint32_t f2tf32(float f) {
    uint32_t r;
    asm("cvt.rna.tf32.f32 %0, %1;" : "=r"(r) : "f"(f));
    return r;
}

__device__ __forceinline__ void mma_tf32(
    float& c0, float& c1, float& c2, float& c3,
    uint32_t a0, uint32_t a1, uint32_t a2, uint32_t a3,
    uint32_t b0, uint32_t b1)
{
    asm volatile(
        "mma.sync.aligned.m16n8k8.row.col.f32.tf32.tf32.f32 "
        "{%0,%1,%2,%3}, {%4,%5,%6,%7}, {%8,%9}, {%0,%1,%2,%3};"
        : "+f"(c0), "+f"(c1), "+f"(c2), "+f"(c3)
        : "r"(a0), "r"(a1), "r"(a2), "r"(a3), "r"(b0), "r"(b1));
}

__device__ __forceinline__ void mma_f16(
    float& c0, float& c1, float& c2, float& c3,
    uint32_t a0, uint32_t a1, uint32_t a2, uint32_t a3,
    uint32_t b0, uint32_t b1)
{
    asm volatile(
        "mma.sync.aligned.m16n8k16.row.col.f32.f16.f16.f32 "
        "{%0,%1,%2,%3}, {%4,%5,%6,%7}, {%8,%9}, {%0,%1,%2,%3};"
        : "+f"(c0), "+f"(c1), "+f"(c2), "+f"(c3)
        : "r"(a0), "r"(a1), "r"(a2), "r"(a3), "r"(b0), "r"(b1));
}

__device__ __forceinline__ uint32_t pack_h2(float lo, float hi) {
    __half2 h = __floats2half2_rn(lo, hi);
    return *(uint32_t*)&h;
}

// ---------------------------------------------------------------------------
// fp16 tensor-core batched GEMM: C[b] (MxN) = A (MxK weights) * X[b] (KxN)
// 256 threads, 128x128x32 tiles. 8 warps (4x2); warp = 32x64 via m16n8k16.
// smem: A[m][k] fp16, X transposed [n][k] fp16 (so every fragment reg is one
// contiguous LDS.32). Conversion to fp16 at load time; f32 accumulate.
// ---------------------------------------------------------------------------
#define AKS 36    // halves per A row (32 + 4 pad)
#define XKS 36    // halves per X row (32 + 4 pad)

template<bool FUSE_ADD, bool RELU>
__device__ __forceinline__ void gemm_tc_body(
    const float* __restrict__ A,
    const float* __restrict__ X0,
    const float* __restrict__ X1,
    float* __restrict__ C,
    int M, int K, int N)
{
    const int b = blockIdx.z;
    const float* X0b = X0 + (size_t)b * K * N;
    const float* X1b = FUSE_ADD ? (X1 + (size_t)b * K * N) : nullptr;
    float* Cb = C + (size_t)b * M * N;

    const int tileM = blockIdx.y * BMT;
    const int tileN = blockIdx.x * BNT;

    __shared__ __half As[BMT][AKS];   // [m][k]
    __shared__ __half Xs[BNT][XKS];   // [n][k]  (transposed)

    const int tid   = threadIdx.x;
    const int warp  = tid >> 5;
    const int lane  = tid & 31;
    const int group = lane >> 2;           // 0..7
    const int tig   = lane & 3;            // 0..3
    const int warp_m = warp >> 1;          // 0..3
    const int warp_n = warp & 1;           // 0..1

    float acc[2][8][4];
#pragma unroll
    for (int mt = 0; mt < 2; mt++)
#pragma unroll
        for (int nt = 0; nt < 8; nt++)
#pragma unroll
            for (int i = 0; i < 4; i++) acc[mt][nt][i] = 0.0f;

    // staged (already fp16-packed) regs for the next tile
    uint32_t ah[4][2];    // A: 4 float4 -> 4x2 half2
    uint32_t xh[2][4];    // X: 2 row-pairs x 4 n -> half2(k, k+1)

    auto load_regs = [&](int k0) {
        // A tile: 128 rows x 32 k = 1024 float4, 4 per thread
#pragma unroll
        for (int i = 0; i < 4; i++) {
            int f = tid + i * 256;          // 0..1023
            int arow = f >> 3, ac4 = f & 7;
            float4 a = *(const float4*)(A + (size_t)(tileM + arow) * K + k0 + ac4 * 4);
            ah[i][0] = pack_h2(a.x, a.y);
            ah[i][1] = pack_h2(a.z, a.w);
        }
        // X tile: 32 k x 128 n, loaded as 16 k-pairs x 32 n4; 2 pairs per thread
#pragma unroll
        for (int p = 0; p < 2; p++) {
            int f = tid + p * 256;          // 0..511
            int kp = f & 15;                // k-pair 0..15
            int n4 = (f >> 4) & 31;         // 0..31
            size_t off = (size_t)(k0 + 2 * kp) * N + tileN + n4 * 4;
            float4 v0 = *(const float4*)(X0b + off);
            float4 v1 = *(const float4*)(X0b + off + N);
            if (FUSE_ADD) {
                float4 p0 = *(const float4*)(X1b + off);
                float4 p1 = *(const float4*)(X1b + off + N);
                v0.x += p0.x; v0.y += p0.y; v0.z += p0.z; v0.w += p0.w;
                v1.x += p1.x; v1.y += p1.y; v1.z += p1.z; v1.w += p1.w;
            }
            xh[p][0] = pack_h2(v0.x, v1.x);
            xh[p][1] = pack_h2(v0.y, v1.y);
            xh[p][2] = pack_h2(v0.z, v1.z);
            xh[p][3] = pack_h2(v0.w, v1.w);
        }
    };

    auto store_smem = [&]() {
#pragma unroll
        for (int i = 0; i < 4; i++) {
            int f = tid + i * 256;
            int arow = f >> 3, ac4 = f & 7;
            *(uint2*)(&As[arow][ac4 * 4]) = make_uint2(ah[i][0], ah[i][1]);
        }
#pragma unroll
        for (int p = 0; p < 2; p++) {
            int f = tid + p * 256;
            int kp = f & 15;
            int n4 = (f >> 4) & 31;
#pragma unroll
            for (int j = 0; j < 4; j++)
                *(uint32_t*)(&Xs[n4 * 4 + j][2 * kp]) = xh[p][j];
        }
    };

    auto compute = [&]() {
#pragma unroll
        for (int ks = 0; ks < 2; ks++) {
            const int kb = ks * 16;
            uint32_t af[2][4];
#pragma unroll
            for (int mt = 0; mt < 2; mt++) {
                int m = warp_m * 32 + mt * 16 + group;
                af[mt][0] = *(const uint32_t*)(&As[m    ][kb + 2 * tig]);
                af[mt][1] = *(const uint32_t*)(&As[m + 8][kb + 2 * tig]);
                af[mt][2] = *(const uint32_t*)(&As[m    ][kb + 2 * tig + 8]);
                af[mt][3] = *(const uint32_t*)(&As[m + 8][kb + 2 * tig + 8]);
            }
            uint32_t bf[8][2];
#pragma unroll
            for (int nt = 0; nt < 8; nt++) {
                int n = warp_n * 64 + nt * 8 + group;
                bf[nt][0] = *(const uint32_t*)(&Xs[n][kb + 2 * tig]);
                bf[nt][1] = *(const uint32_t*)(&Xs[n][kb + 2 * tig + 8]);
            }
#pragma unroll
            for (int mt = 0; mt < 2; mt++)
#pragma unroll
                for (int nt = 0; nt < 8; nt++)
                    mma_f16(acc[mt][nt][0], acc[mt][nt][1],
                            acc[mt][nt][2], acc[mt][nt][3],
                            af[mt][0], af[mt][1], af[mt][2], af[mt][3],
                            bf[nt][0], bf[nt][1]);
        }
    };

    load_regs(0);
    store_smem();
    __syncthreads();

#pragma unroll 1
    for (int k0 = BKT; k0 < K; k0 += BKT) {
        load_regs(k0);       // ldg + cvt overlaps with compute below
        compute();
        __syncthreads();
        store_smem();
        __syncthreads();
    }
    compute();

    // ---- epilogue ----
#pragma unroll
    for (int mt = 0; mt < 2; mt++) {
        int r = tileM + warp_m * 32 + mt * 16 + group;
#pragma unroll
        for (int nt = 0; nt < 8; nt++) {
            int c = tileN + warp_n * 64 + nt * 8 + tig * 2;
            float2 v0, v1;
            v0.x = acc[mt][nt][0]; v0.y = acc[mt][nt][1];
            v1.x = acc[mt][nt][2]; v1.y = acc[mt][nt][3];
            if (RELU) {
                v0.x = fmaxf(v0.x, 0.0f); v0.y = fmaxf(v0.y, 0.0f);
                v1.x = fmaxf(v1.x, 0.0f); v1.y = fmaxf(v1.y, 0.0f);
            }
            *(float2*)(Cb + (size_t)r * N + c)       = v0;
            *(float2*)(Cb + (size_t)(r + 8) * N + c) = v1;
        }
    }
}

__global__ __launch_bounds__(256) void gemm_qk(
    const float* __restrict__ A, const float* __restrict__ x,
    const float* __restrict__ pos)
{
    gemm_tc_body<true, true>(A, x, pos, g_QK, 1024, CCH, NPIX);
}

__global__ __launch_bounds__(256) void gemm_v(
    const float* __restrict__ A, const float* __restrict__ x)
{
    gemm_tc_body<false, false>(A, x, nullptr, g_V, 512, CCH, NPIX);
}

__global__ __launch_bounds__(256) void gemm_o(
    const float* __restrict__ A, float* __restrict__ out)
{
    gemm_tc_body<false, false>(A, g_V, nullptr, out, 512, CCH, NPIX);
}

// ---------------------------------------------------------------------------
// KV kernel (tensor-core, tf32), unchanged from R5 (the 1354.8us baseline).
// ---------------------------------------------------------------------------
#define KVS 68

__global__ __launch_bounds__(256) void kv_mma_kernel()
{
    const int bh = blockIdx.x;
    const int b = bh >> 3, h = bh & 7;
    const float* kp = g_QK + ((size_t)b * 1024 + 512 + h * 64) * NPIX;
    const float* vp = g_V  + ((size_t)b * 512  +       h * 64) * NPIX;

    __shared__ uint32_t Vs[80][KVS];
    __shared__ uint32_t Ks[64][KVS];

    const int tid  = threadIdx.x;
    const int warp = tid >> 5;
    const int lane = tid & 31;
    const int group = lane >> 2;
    const int tig   = lane & 3;

    for (int i = tid; i < 16 * KVS; i += 256) {
        int r = 64 + i / KVS, c = i % KVS;
        Vs[r][c] = (r == 64) ? __float_as_uint(1.0f) : 0u;
    }

    float acc[5][4];
#pragma unroll
    for (int mt = 0; mt < 5; mt++)
#pragma unroll
        for (int i = 0; i < 4; i++) acc[mt][i] = 0.0f;

    for (int n0 = 0; n0 < NPIX; n0 += 64) {
        __syncthreads();
#pragma unroll
        for (int i = 0; i < 4; i++) {
            int f = tid + i * 256;
            int row = f >> 4, c4 = f & 15;
            float4 v = *(const float4*)(vp + (size_t)row * NPIX + n0 + c4 * 4);
            uint4 vt;
            vt.x = f2tf32(v.x); vt.y = f2tf32(v.y); vt.z = f2tf32(v.z); vt.w = f2tf32(v.w);
            *(uint4*)(&Vs[row][c4 * 4]) = vt;
            float4 kk = *(const float4*)(kp + (size_t)row * NPIX + n0 + c4 * 4);
            uint4 kt;
            kt.x = f2tf32(kk.x); kt.y = f2tf32(kk.y); kt.z = f2tf32(kk.z); kt.w = f2tf32(kk.w);
            *(uint4*)(&Ks[row][c4 * 4]) = kt;
        }
        __syncthreads();

#pragma unroll
        for (int ks = 0; ks < 8; ks++) {
            const int k = ks * 8;
            uint32_t b0 = Ks[warp * 8 + group][k + tig];
            uint32_t b1 = Ks[warp * 8 + group][k + tig + 4];
#pragma unroll
            for (int mt = 0; mt < 5; mt++) {
                int r = mt * 16 + group;
                uint32_t a0 = Vs[r    ][k + tig];
                uint32_t a1 = Vs[r + 8][k + tig];
                uint32_t a2 = Vs[r    ][k + tig + 4];
                uint32_t a3 = Vs[r + 8][k + tig + 4];
                mma_tf32(acc[mt][0], acc[mt][1], acc[mt][2], acc[mt][3],
                         a0, a1, a2, a3, b0, b1);
            }
        }
    }

    float* kvb = g_KV + (size_t)bh * 65 * 64;
#pragma unroll
    for (int mt = 0; mt < 5; mt++) {
        int r0 = mt * 16 + group;
        int r1 = r0 + 8;
        int c = warp * 8 + tig * 2;
        if (r0 < 65) {
            kvb[r0 * 64 + c]     = acc[mt][0];
            kvb[r0 * 64 + c + 1] = acc[mt][1];
        }
        if (r1 < 65) {
            kvb[r1 * 64 + c]     = acc[mt][2];
            kvb[r1 * 64 + c + 1] = acc[mt][3];
        }
    }
}

// ---------------------------------------------------------------------------
// Attention output (tensor-core, tf32), unchanged from R5.
// ---------------------------------------------------------------------------
#define QS 136

__global__ __launch_bounds__(256) void attn_mma_kernel()
{
    const int bh = blockIdx.y;
    const int b = bh >> 3, h = bh & 7;
    const int ntile = blockIdx.x * 128;

    __shared__ uint32_t As[80][KVS];
    __shared__ uint32_t Qs[64][QS];
    __shared__ float norms[8][16];

    const int tid  = threadIdx.x;
    const int warp = tid >> 5;
    const int lane = tid & 31;
    const int group = lane >> 2;
    const int tig   = lane & 3;

    const float* kvb = g_KV + (size_t)bh * 65 * 64;
    for (int i = tid; i < 80 * 64; i += 256) {
        int r = i >> 6, c = i & 63;
        As[r][c] = (r < 65) ? f2tf32(kvb[i]) : 0u;
    }
    const float* q = g_QK + ((size_t)b * 1024 + h * 64) * NPIX + ntile;
#pragma unroll
    for (int i = 0; i < 8; i++) {
        int f = tid + i * 256;
        int row = f >> 5, c4 = f & 31;
        float4 v = *(const float4*)(q + (size_t)row * NPIX + c4 * 4);
        uint4 t;
        t.x = f2tf32(v.x); t.y = f2tf32(v.y); t.z = f2tf32(v.z); t.w = f2tf32(v.w);
        *(uint4*)(&Qs[row][c4 * 4]) = t;
    }
    __syncthreads();

    float acc[5][2][4];
#pragma unroll
    for (int mt = 0; mt < 5; mt++)
#pragma unroll
        for (int nt = 0; nt < 2; nt++)
#pragma unroll
            for (int i = 0; i < 4; i++) acc[mt][nt][i] = 0.0f;

#pragma unroll
    for (int ks = 0; ks < 8; ks++) {
        const int k = ks * 8;
        uint32_t bf[2][2];
#pragma unroll
        for (int nt = 0; nt < 2; nt++) {
            int c = warp * 16 + nt * 8 + group;
            bf[nt][0] = Qs[k + tig    ][c];
            bf[nt][1] = Qs[k + tig + 4][c];
        }
#pragma unroll
        for (int mt = 0; mt < 5; mt++) {
            int r = mt * 16 + group;
            uint32_t a0 = As[r    ][k + tig];
            uint32_t a1 = As[r + 8][k + tig];
            uint32_t a2 = As[r    ][k + tig + 4];
            uint32_t a3 = As[r + 8][k + tig + 4];
#pragma unroll
            for (int nt = 0; nt < 2; nt++)
                mma_tf32(acc[mt][nt][0], acc[mt][nt][1],
                         acc[mt][nt][2], acc[mt][nt][3],
                         a0, a1, a2, a3, bf[nt][0], bf[nt][1]);
        }
    }

    if (group == 0) {
#pragma unroll
        for (int nt = 0; nt < 2; nt++) {
            norms[warp][nt * 8 + tig * 2]     = acc[4][nt][0];
            norms[warp][nt * 8 + tig * 2 + 1] = acc[4][nt][1];
        }
    }
    __syncwarp();

    float* ob = g_V + ((size_t)b * 512 + h * 64) * NPIX + ntile;
#pragma unroll
    for (int nt = 0; nt < 2; nt++) {
        int cl = nt * 8 + tig * 2;
        float inv0 = 1.0f / (norms[warp][cl]     + EPS);
        float inv1 = 1.0f / (norms[warp][cl + 1] + EPS);
        int c = warp * 16 + cl;
#pragma unroll
        for (int mt = 0; mt < 4; mt++) {
            int r0 = mt * 16 + group;
            float2 v0, v1;
            v0.x = acc[mt][nt][0] * inv0; v0.y = acc[mt][nt][1] * inv1;
            v1.x = acc[mt][nt][2] * inv0; v1.y = acc[mt][nt][3] * inv1;
            *(float2*)(ob + (size_t)r0 * NPIX + c)       = v0;
            *(float2*)(ob + (size_t)(r0 + 8) * NPIX + c) = v1;
        }
    }
}

// ---------------------------------------------------------------------------
extern "C" void kernel_launch(void* const* d_in, const int* in_sizes, int n_in,
                              void* d_out, int out_size)
{
    const float* x    = (const float*)d_in[0];
    const float* pos  = (const float*)d_in[1];
    const float* w_qk = (const float*)d_in[2];
    const float* w_v  = (const float*)d_in[3];
    const float* w_o  = (const float*)d_in[4];
    float* out = (float*)d_out;

    dim3 thr(256);

    // 1) qk = relu(w_qk @ (x+pos))   [B,1024,N]
    gemm_qk<<<dim3(NPIX / BNT, 1024 / BMT, BATCH), thr>>>(w_qk, x, pos);

    // 2) v = w_v @ x                 [B,512,N]
    gemm_v<<<dim3(NPIX / BNT, 512 / BMT, BATCH), thr>>>(w_v, x);

    // 3) kv = v_pad @ k^T            [B,H,65,64]
    kv_mma_kernel<<<BATCH * NHEAD, 256>>>();

    // 4) out = normalize(kv @ q)     [B,512,N]  in-place over g_V
    attn_mma_kernel<<<dim3(NPIX / 128, BATCH * NHEAD), 256>>>();

    // 5) final = w_o @ out           [B,512,N]
    gemm_o<<<dim3(NPIX / BNT, 512 / BMT, BATCH), thr>>>(w_o, out);
}

// round 11
// speedup vs baseline: 1.2681x; 1.2681x over previous
#include <cuda_runtime.h>
#include <cstdint>

// Problem constants
#define BATCH 16
#define CCH   512
#define NPIX  4096          // 64*64
#define NHEAD 8
#define HDIM  64
#define EPS   1e-6f

// Tensor-core GEMM tile config
#define BMT 128
#define BNT 128
#define BKT 32

#define KV_SPLIT 4
#define KV_CHUNK (NPIX / KV_SPLIT)   // 1024 pixels per split

// Scratch (device globals - no allocation at launch time).
__device__ float g_QK [(size_t)BATCH * 1024 * NPIX];  // relu(w_qk@(x+pos)): q=ch0..511, k=ch512..1023
__device__ float g_V  [(size_t)BATCH * CCH  * NPIX];  // V, then attention output (reused)
__device__ float g_KV [(size_t)BATCH * NHEAD * 65 * 64];
__device__ float g_KVp[(size_t)KV_SPLIT * BATCH * NHEAD * 65 * 64];   // kv partials

// ---------------------------------------------------------------------------
// tf32 helpers
// ---------------------------------------------------------------------------
__device__ __forceinline__ uint32_t f2tf32(float f) {
    uint32_t r;
    asm("cvt.rna.tf32.f32 %0, %1;" : "=r"(r) : "f"(f));
    return r;
}

__device__ __forceinline__ void mma_tf32(
    float& c0, float& c1, float& c2, float& c3,
    uint32_t a0, uint32_t a1, uint32_t a2, uint32_t a3,
    uint32_t b0, uint32_t b1)
{
    asm volatile(
        "mma.sync.aligned.m16n8k8.row.col.f32.tf32.tf32.f32 "
        "{%0,%1,%2,%3}, {%4,%5,%6,%7}, {%8,%9}, {%0,%1,%2,%3};"
        : "+f"(c0), "+f"(c1), "+f"(c2), "+f"(c3)
        : "r"(a0), "r"(a1), "r"(a2), "r"(a3), "r"(b0), "r"(b1));
}

// ---------------------------------------------------------------------------
// tf32 tensor-core batched GEMM (R5 layout, now 2-stage double-buffered).
// C[b] (MxN) = A (MxK weights) * X[b] (KxN). 256 threads, 128x128x32 tiles.
// 8 warps (4x2); each warp computes 32x64 via m16n8k8 tf32 mma.
// One __syncthreads per K-tile; store goes to the alternate stage.
// ---------------------------------------------------------------------------
#define ASZ (BMT * 36)     // A stage words (stride 36)
#define XSZ (BKT * 136)    // X stage words (stride 136)
#define STG (ASZ + XSZ)
#define GEMM_SMEM_BYTES (2 * STG * 4)   // 71680 B

template<bool FUSE_ADD, bool RELU>
__device__ __forceinline__ void gemm_tc_body(
    const float* __restrict__ A,
    const float* __restrict__ X0,
    const float* __restrict__ X1,
    float* __restrict__ C,
    int M, int K, int N)
{
    extern __shared__ uint32_t dsm[];

    const int b = blockIdx.z;
    const float* X0b = X0 + (size_t)b * K * N;
    const float* X1b = FUSE_ADD ? (X1 + (size_t)b * K * N) : nullptr;
    float* Cb = C + (size_t)b * M * N;

    const int tileM = blockIdx.y * BMT;
    const int tileN = blockIdx.x * BNT;

    const int tid   = threadIdx.x;
    const int warp  = tid >> 5;
    const int lane  = tid & 31;
    const int group = lane >> 2;           // 0..7
    const int tig   = lane & 3;            // 0..3
    const int warp_m = warp >> 1;          // 0..3
    const int warp_n = warp & 1;           // 0..1
    const int m0 = warp_m * 32;
    const int n0 = warp_n * 64;

    float acc[2][8][4];
#pragma unroll
    for (int mt = 0; mt < 2; mt++)
#pragma unroll
        for (int nt = 0; nt < 8; nt++)
#pragma unroll
            for (int i = 0; i < 4; i++) acc[mt][nt][i] = 0.0f;

    float4 ar[4], xv[4];    // staging registers for the next tile

    auto load_regs = [&](int k0) {
#pragma unroll
        for (int i = 0; i < 4; i++) {
            int f = tid + i * 256;         // 0..1023 (float4 index)
            int arow = f >> 3, ac4 = f & 7;
            ar[i] = *(const float4*)(A + (size_t)(tileM + arow) * K + k0 + ac4 * 4);
            int krow = f >> 5, n4 = f & 31;
            size_t off = (size_t)(k0 + krow) * N + tileN + n4 * 4;
            float4 v = *(const float4*)(X0b + off);
            if (FUSE_ADD) {
                float4 p = *(const float4*)(X1b + off);
                v.x += p.x; v.y += p.y; v.z += p.z; v.w += p.w;
            }
            xv[i] = v;
        }
    };

    auto store_smem = [&](int s) {
        uint32_t* As = dsm + s * STG;
        uint32_t* Xs = dsm + s * STG + ASZ;
#pragma unroll
        for (int i = 0; i < 4; i++) {
            int f = tid + i * 256;
            int arow = f >> 3, ac4 = f & 7;
            uint4 at;
            at.x = f2tf32(ar[i].x); at.y = f2tf32(ar[i].y);
            at.z = f2tf32(ar[i].z); at.w = f2tf32(ar[i].w);
            *(uint4*)(As + arow * 36 + ac4 * 4) = at;
            int krow = f >> 5, n4 = f & 31;
            uint4 xt;
            xt.x = f2tf32(xv[i].x); xt.y = f2tf32(xv[i].y);
            xt.z = f2tf32(xv[i].z); xt.w = f2tf32(xv[i].w);
            *(uint4*)(Xs + krow * 136 + n4 * 4) = xt;
        }
    };

    auto compute = [&](int s) {
        const uint32_t* As = dsm + s * STG;
        const uint32_t* Xs = dsm + s * STG + ASZ;
#pragma unroll
        for (int ks = 0; ks < BKT / 8; ks++) {
            const int k = ks * 8;
            uint32_t af[2][4];
#pragma unroll
            for (int mt = 0; mt < 2; mt++) {
                int r = m0 + mt * 16 + group;
                af[mt][0] = As[r * 36 + k + tig];
                af[mt][1] = As[(r + 8) * 36 + k + tig];
                af[mt][2] = As[r * 36 + k + tig + 4];
                af[mt][3] = As[(r + 8) * 36 + k + tig + 4];
            }
            uint32_t bf[8][2];
#pragma unroll
            for (int nt = 0; nt < 8; nt++) {
                int c = n0 + nt * 8 + group;
                bf[nt][0] = Xs[(k + tig) * 136 + c];
                bf[nt][1] = Xs[(k + tig + 4) * 136 + c];
            }
#pragma unroll
            for (int mt = 0; mt < 2; mt++)
#pragma unroll
                for (int nt = 0; nt < 8; nt++)
                    mma_tf32(acc[mt][nt][0], acc[mt][nt][1],
                             acc[mt][nt][2], acc[mt][nt][3],
                             af[mt][0], af[mt][1], af[mt][2], af[mt][3],
                             bf[nt][0], bf[nt][1]);
        }
    };

    const int NK = K / BKT;   // 16
    load_regs(0);
    store_smem(0);
    __syncthreads();

#pragma unroll 1
    for (int t = 0; t < NK; t++) {
        if (t + 1 < NK) load_regs((t + 1) * BKT);   // LDG overlaps compute
        compute(t & 1);
        if (t + 1 < NK) {
            store_smem((t + 1) & 1);   // alternate stage: no pre-store barrier needed
            __syncthreads();
        }
    }

    // ---- epilogue ----
#pragma unroll
    for (int mt = 0; mt < 2; mt++) {
        int r = tileM + m0 + mt * 16 + group;
#pragma unroll
        for (int nt = 0; nt < 8; nt++) {
            int c = tileN + n0 + nt * 8 + tig * 2;
            float2 v0, v1;
            v0.x = acc[mt][nt][0]; v0.y = acc[mt][nt][1];
            v1.x = acc[mt][nt][2]; v1.y = acc[mt][nt][3];
            if (RELU) {
                v0.x = fmaxf(v0.x, 0.0f); v0.y = fmaxf(v0.y, 0.0f);
                v1.x = fmaxf(v1.x, 0.0f); v1.y = fmaxf(v1.y, 0.0f);
            }
            *(float2*)(Cb + (size_t)r * N + c)       = v0;
            *(float2*)(Cb + (size_t)(r + 8) * N + c) = v1;
        }
    }
}

__global__ __launch_bounds__(256) void gemm_qk(
    const float* __restrict__ A, const float* __restrict__ x,
    const float* __restrict__ pos)
{
    gemm_tc_body<true, true>(A, x, pos, g_QK, 1024, CCH, NPIX);
}

__global__ __launch_bounds__(256) void gemm_v(
    const float* __restrict__ A, const float* __restrict__ x)
{
    gemm_tc_body<false, false>(A, x, nullptr, g_V, 512, CCH, NPIX);
}

__global__ __launch_bounds__(256) void gemm_o(
    const float* __restrict__ A, float* __restrict__ out)
{
    gemm_tc_body<false, false>(A, g_V, nullptr, out, 512, CCH, NPIX);
}

// ---------------------------------------------------------------------------
// KV kernel (tensor-core, tf32), split 4-way over N for occupancy.
// grid (128, KV_SPLIT): blockIdx.x = bh, blockIdx.y = split index.
// Each block computes a partial KV over its 1024-pixel chunk -> g_KVp.
// ---------------------------------------------------------------------------
#define KVS 68

__global__ __launch_bounds__(256) void kv_mma_kernel()
{
    const int bh = blockIdx.x;
    const int sp = blockIdx.y;
    const int b = bh >> 3, h = bh & 7;
    const float* kp = g_QK + ((size_t)b * 1024 + 512 + h * 64) * NPIX;
    const float* vp = g_V  + ((size_t)b * 512  +       h * 64) * NPIX;

    __shared__ uint32_t Vs[80][KVS];
    __shared__ uint32_t Ks[64][KVS];

    const int tid  = threadIdx.x;
    const int warp = tid >> 5;
    const int lane = tid & 31;
    const int group = lane >> 2;
    const int tig   = lane & 3;

    for (int i = tid; i < 16 * KVS; i += 256) {
        int r = 64 + i / KVS, c = i % KVS;
        Vs[r][c] = (r == 64) ? __float_as_uint(1.0f) : 0u;
    }

    float acc[5][4];
#pragma unroll
    for (int mt = 0; mt < 5; mt++)
#pragma unroll
        for (int i = 0; i < 4; i++) acc[mt][i] = 0.0f;

    const int nbeg = sp * KV_CHUNK;
    const int nend = nbeg + KV_CHUNK;
    for (int n0 = nbeg; n0 < nend; n0 += 64) {
        __syncthreads();
#pragma unroll
        for (int i = 0; i < 4; i++) {
            int f = tid + i * 256;
            int row = f >> 4, c4 = f & 15;
            float4 v = *(const float4*)(vp + (size_t)row * NPIX + n0 + c4 * 4);
            uint4 vt;
            vt.x = f2tf32(v.x); vt.y = f2tf32(v.y); vt.z = f2tf32(v.z); vt.w = f2tf32(v.w);
            *(uint4*)(&Vs[row][c4 * 4]) = vt;
            float4 kk = *(const float4*)(kp + (size_t)row * NPIX + n0 + c4 * 4);
            uint4 kt;
            kt.x = f2tf32(kk.x); kt.y = f2tf32(kk.y); kt.z = f2tf32(kk.z); kt.w = f2tf32(kk.w);
            *(uint4*)(&Ks[row][c4 * 4]) = kt;
        }
        __syncthreads();

#pragma unroll
        for (int ks = 0; ks < 8; ks++) {
            const int k = ks * 8;
            uint32_t b0 = Ks[warp * 8 + group][k + tig];
            uint32_t b1 = Ks[warp * 8 + group][k + tig + 4];
#pragma unroll
            for (int mt = 0; mt < 5; mt++) {
                int r = mt * 16 + group;
                uint32_t a0 = Vs[r    ][k + tig];
                uint32_t a1 = Vs[r + 8][k + tig];
                uint32_t a2 = Vs[r    ][k + tig + 4];
                uint32_t a3 = Vs[r + 8][k + tig + 4];
                mma_tf32(acc[mt][0], acc[mt][1], acc[mt][2], acc[mt][3],
                         a0, a1, a2, a3, b0, b1);
            }
        }
    }

    float* kvb = g_KVp + ((size_t)sp * BATCH * NHEAD + bh) * 65 * 64;
#pragma unroll
    for (int mt = 0; mt < 5; mt++) {
        int r0 = mt * 16 + group;
        int r1 = r0 + 8;
        int c = warp * 8 + tig * 2;
        if (r0 < 65) {
            kvb[r0 * 64 + c]     = acc[mt][0];
            kvb[r0 * 64 + c + 1] = acc[mt][1];
        }
        if (r1 < 65) {
            kvb[r1 * 64 + c]     = acc[mt][2];
            kvb[r1 * 64 + c + 1] = acc[mt][3];
        }
    }
}

// Reduce partial KVs: g_KV[bh] = sum_sp g_KVp[sp][bh]
__global__ __launch_bounds__(256) void kv_reduce_kernel()
{
    const int bh = blockIdx.x;
    const size_t stride = (size_t)BATCH * NHEAD * 65 * 64;
    float* dst = g_KV + (size_t)bh * 65 * 64;
    const float* src = g_KVp + (size_t)bh * 65 * 64;
    for (int i = threadIdx.x; i < 65 * 64; i += 256) {
        float s = src[i];
#pragma unroll
        for (int sp = 1; sp < KV_SPLIT; sp++)
            s += src[sp * stride + i];
        dst[i] = s;
    }
}

// ---------------------------------------------------------------------------
// Attention output (tensor-core, tf32), unchanged from R5.
// ---------------------------------------------------------------------------
#define QS 136

__global__ __launch_bounds__(256) void attn_mma_kernel()
{
    const int bh = blockIdx.y;
    const int b = bh >> 3, h = bh & 7;
    const int ntile = blockIdx.x * 128;

    __shared__ uint32_t As[80][KVS];
    __shared__ uint32_t Qs[64][QS];
    __shared__ float norms[8][16];

    const int tid  = threadIdx.x;
    const int warp = tid >> 5;
    const int lane = tid & 31;
    const int group = lane >> 2;
    const int tig   = lane & 3;

    const float* kvb = g_KV + (size_t)bh * 65 * 64;
    for (int i = tid; i < 80 * 64; i += 256) {
        int r = i >> 6, c = i & 63;
        As[r][c] = (r < 65) ? f2tf32(kvb[i]) : 0u;
    }
    const float* q = g_QK + ((size_t)b * 1024 + h * 64) * NPIX + ntile;
#pragma unroll
    for (int i = 0; i < 8; i++) {
        int f = tid + i * 256;
        int row = f >> 5, c4 = f & 31;
        float4 v = *(const float4*)(q + (size_t)row * NPIX + c4 * 4);
        uint4 t;
        t.x = f2tf32(v.x); t.y = f2tf32(v.y); t.z = f2tf32(v.z); t.w = f2tf32(v.w);
        *(uint4*)(&Qs[row][c4 * 4]) = t;
    }
    __syncthreads();

    float acc[5][2][4];
#pragma unroll
    for (int mt = 0; mt < 5; mt++)
#pragma unroll
        for (int nt = 0; nt < 2; nt++)
#pragma unroll
            for (int i = 0; i < 4; i++) acc[mt][nt][i] = 0.0f;

#pragma unroll
    for (int ks = 0; ks < 8; ks++) {
        const int k = ks * 8;
        uint32_t bf[2][2];
#pragma unroll
        for (int nt = 0; nt < 2; nt++) {
            int c = warp * 16 + nt * 8 + group;
            bf[nt][0] = Qs[k + tig    ][c];
            bf[nt][1] = Qs[k + tig + 4][c];
        }
#pragma unroll
        for (int mt = 0; mt < 5; mt++) {
            int r = mt * 16 + group;
            uint32_t a0 = As[r    ][k + tig];
            uint32_t a1 = As[r + 8][k + tig];
            uint32_t a2 = As[r    ][k + tig + 4];
            uint32_t a3 = As[r + 8][k + tig + 4];
#pragma unroll
            for (int nt = 0; nt < 2; nt++)
                mma_tf32(acc[mt][nt][0], acc[mt][nt][1],
                         acc[mt][nt][2], acc[mt][nt][3],
                         a0, a1, a2, a3, bf[nt][0], bf[nt][1]);
        }
    }

    if (group == 0) {
#pragma unroll
        for (int nt = 0; nt < 2; nt++) {
            norms[warp][nt * 8 + tig * 2]     = acc[4][nt][0];
            norms[warp][nt * 8 + tig * 2 + 1] = acc[4][nt][1];
        }
    }
    __syncwarp();

    float* ob = g_V + ((size_t)b * 512 + h * 64) * NPIX + ntile;
#pragma unroll
    for (int nt = 0; nt < 2; nt++) {
        int cl = nt * 8 + tig * 2;
        float inv0 = 1.0f / (norms[warp][cl]     + EPS);
        float inv1 = 1.0f / (norms[warp][cl + 1] + EPS);
        int c = warp * 16 + cl;
#pragma unroll
        for (int mt = 0; mt < 4; mt++) {
            int r0 = mt * 16 + group;
            float2 v0, v1;
            v0.x = acc[mt][nt][0] * inv0; v0.y = acc[mt][nt][1] * inv1;
            v1.x = acc[mt][nt][2] * inv0; v1.y = acc[mt][nt][3] * inv1;
            *(float2*)(ob + (size_t)r0 * NPIX + c)       = v0;
            *(float2*)(ob + (size_t)(r0 + 8) * NPIX + c) = v1;
        }
    }
}

// ---------------------------------------------------------------------------
extern "C" void kernel_launch(void* const* d_in, const int* in_sizes, int n_in,
                              void* d_out, int out_size)
{
    const float* x    = (const float*)d_in[0];
    const float* pos  = (const float*)d_in[1];
    const float* w_qk = (const float*)d_in[2];
    const float* w_v  = (const float*)d_in[3];
    const float* w_o  = (const float*)d_in[4];
    float* out = (float*)d_out;

    cudaFuncSetAttribute(gemm_qk, cudaFuncAttributeMaxDynamicSharedMemorySize, GEMM_SMEM_BYTES);
    cudaFuncSetAttribute(gemm_v,  cudaFuncAttributeMaxDynamicSharedMemorySize, GEMM_SMEM_BYTES);
    cudaFuncSetAttribute(gemm_o,  cudaFuncAttributeMaxDynamicSharedMemorySize, GEMM_SMEM_BYTES);

    dim3 thr(256);

    // 1) qk = relu(w_qk @ (x+pos))   [B,1024,N]
    gemm_qk<<<dim3(NPIX / BNT, 1024 / BMT, BATCH), thr, GEMM_SMEM_BYTES>>>(w_qk, x, pos);

    // 2) v = w_v @ x                 [B,512,N]
    gemm_v<<<dim3(NPIX / BNT, 512 / BMT, BATCH), thr, GEMM_SMEM_BYTES>>>(w_v, x);

    // 3) kv partials + reduce        [B,H,65,64]
    kv_mma_kernel<<<dim3(BATCH * NHEAD, KV_SPLIT), 256>>>();
    kv_reduce_kernel<<<BATCH * NHEAD, 256>>>();

    // 4) out = normalize(kv @ q)     [B,512,N]  in-place over g_V
    attn_mma_kernel<<<dim3(NPIX / 128, BATCH * NHEAD), 256>>>();

    // 5) final = w_o @ out           [B,512,N]
    gemm_o<<<dim3(NPIX / BNT, 512 / BMT, BATCH), thr, GEMM_SMEM_BYTES>>>(w_o, out);
}

// round 13
// speedup vs baseline: 1.9287x; 1.5210x over previous
#include <cuda_runtime.h>
#include <cuda_fp16.h>
#include <cstdint>

// Problem constants
#define BATCH 16
#define CCH   512
#define NPIX  4096          // 64*64
#define NHEAD 8
#define EPS   1e-6f

#define KV_SPLIT 4
#define KV_CHUNK (NPIX / KV_SPLIT)

// Scratch (device globals - no allocation at launch time).
__device__ float g_QK [(size_t)BATCH * 1024 * NPIX];
__device__ float g_V  [(size_t)BATCH * CCH  * NPIX];
__device__ float g_KV [(size_t)BATCH * NHEAD * 65 * 64];
__device__ float g_KVp[(size_t)KV_SPLIT * BATCH * NHEAD * 65 * 64];

// ---------------------------------------------------------------------------
// helpers
// ---------------------------------------------------------------------------
__device__ __forceinline__ uint32_t f2tf32(float f) {
    uint32_t r;
    asm("cvt.rna.tf32.f32 %0, %1;" : "=r"(r) : "f"(f));
    return r;
}

__device__ __forceinline__ void mma_tf32(
    float& c0, float& c1, float& c2, float& c3,
    uint32_t a0, uint32_t a1, uint32_t a2, uint32_t a3,
    uint32_t b0, uint32_t b1)
{
    asm volatile(
        "mma.sync.aligned.m16n8k8.row.col.f32.tf32.tf32.f32 "
        "{%0,%1,%2,%3}, {%4,%5,%6,%7}, {%8,%9}, {%0,%1,%2,%3};"
        : "+f"(c0), "+f"(c1), "+f"(c2), "+f"(c3)
        : "r"(a0), "r"(a1), "r"(a2), "r"(a3), "r"(b0), "r"(b1));
}

__device__ __forceinline__ void mma_f16(
    float& c0, float& c1, float& c2, float& c3,
    uint32_t a0, uint32_t a1, uint32_t a2, uint32_t a3,
    uint32_t b0, uint32_t b1)
{
    asm volatile(
        "mma.sync.aligned.m16n8k16.row.col.f32.f16.f16.f32 "
        "{%0,%1,%2,%3}, {%4,%5,%6,%7}, {%8,%9}, {%0,%1,%2,%3};"
        : "+f"(c0), "+f"(c1), "+f"(c2), "+f"(c3)
        : "r"(a0), "r"(a1), "r"(a2), "r"(a3), "r"(b0), "r"(b1));
}

__device__ __forceinline__ uint32_t pack_h2(float lo, float hi) {
    __half2 h = __floats2half2_rn(lo, hi);
    return *(uint32_t*)&h;
}

__device__ __forceinline__ uint32_t smem_u32(const void* p) {
    uint32_t a;
    asm("{ .reg .u64 t; cvta.to.shared.u64 t, %1; cvt.u32.u64 %0, t; }"
        : "=r"(a) : "l"(p));
    return a;
}

__device__ __forceinline__ void ldsm_x4(
    uint32_t& r0, uint32_t& r1, uint32_t& r2, uint32_t& r3, uint32_t addr)
{
    asm volatile("ldmatrix.sync.aligned.m8n8.x4.shared.b16 {%0,%1,%2,%3}, [%4];"
        : "=r"(r0), "=r"(r1), "=r"(r2), "=r"(r3) : "r"(addr));
}

__device__ __forceinline__ void ldsm_x4_t(
    uint32_t& r0, uint32_t& r1, uint32_t& r2, uint32_t& r3, uint32_t addr)
{
    asm volatile("ldmatrix.sync.aligned.m8n8.x4.trans.shared.b16 {%0,%1,%2,%3}, [%4];"
        : "=r"(r0), "=r"(r1), "=r"(r2), "=r"(r3) : "r"(addr));
}

// ---------------------------------------------------------------------------
// fp16+ldmatrix tensor-core batched GEMM: C[b](MxN) = A(MxK) * X[b](KxN).
// 256 threads, 128x128x32 tiles. 8 warps (4x2); warp = 32x64 via m16n8k16.
// A smem [m][k] fp16 (stride 40 halves), X smem [k][n] fp16 (stride 136) --
// both ldmatrix conflict-free by bank walk. Coalesced gmem loads (R5 pattern).
// ---------------------------------------------------------------------------
#define AKH 40     // halves per A row (32 + 8 pad) -> 20-word stride
#define XKH 136    // halves per X row (128 + 8 pad) -> 68-word stride

template<bool FUSE_ADD, bool RELU>
__device__ __forceinline__ void gemm_tc_body(
    const float* __restrict__ A,
    const float* __restrict__ X0,
    const float* __restrict__ X1,
    float* __restrict__ C,
    int M, int K, int N)
{
    const int b = blockIdx.z;
    const float* X0b = X0 + (size_t)b * K * N;
    const float* X1b = FUSE_ADD ? (X1 + (size_t)b * K * N) : nullptr;
    float* Cb = C + (size_t)b * M * N;

    const int tileM = blockIdx.y * 128;
    const int tileN = blockIdx.x * 128;

    __shared__ __half As[128][AKH];   // [m][k]
    __shared__ __half Xs[32][XKH];    // [k][n]

    const int tid   = threadIdx.x;
    const int warp  = tid >> 5;
    const int lane  = tid & 31;
    const int group = lane >> 2;
    const int tig   = lane & 3;
    const int warp_m = warp >> 1;          // 0..3
    const int warp_n = warp & 1;           // 0..1
    const int m0  = warp_m * 32;
    const int n0w = warp_n * 64;

    // ldmatrix lane-address offsets
    const int rowoff = (lane & 7) + ((lane >> 3) & 1) * 8;   // 0..15
    const int hioff  = (lane >= 16) ? 8 : 0;

    uint32_t a_addr[2], b_addr[4];
#pragma unroll
    for (int mt = 0; mt < 2; mt++)
        a_addr[mt] = smem_u32(&As[m0 + mt * 16 + rowoff][hioff]);
#pragma unroll
    for (int np = 0; np < 4; np++)
        b_addr[np] = smem_u32(&Xs[rowoff][n0w + np * 16 + hioff]);

    float acc[2][8][4];
#pragma unroll
    for (int mt = 0; mt < 2; mt++)
#pragma unroll
        for (int nt = 0; nt < 8; nt++)
#pragma unroll
            for (int i = 0; i < 4; i++) acc[mt][nt][i] = 0.0f;

    // staging (fp16-packed) regs for the next tile
    uint32_t ah[4][2], xh[4][2];

    auto load_regs = [&](int k0) {
#pragma unroll
        for (int i = 0; i < 4; i++) {
            int f = tid + i * 256;          // 0..1023
            // A: [128 m][32 k], coalesced
            int arow = f >> 3, ac4 = f & 7;
            float4 a = *(const float4*)(A + (size_t)(tileM + arow) * K + k0 + ac4 * 4);
            ah[i][0] = pack_h2(a.x, a.y);
            ah[i][1] = pack_h2(a.z, a.w);
            // X: [32 k][128 n], coalesced (full row per warp, R5 pattern)
            int krow = f >> 5, n4 = f & 31;
            size_t off = (size_t)(k0 + krow) * N + tileN + n4 * 4;
            float4 v = *(const float4*)(X0b + off);
            if (FUSE_ADD) {
                float4 p = *(const float4*)(X1b + off);
                v.x += p.x; v.y += p.y; v.z += p.z; v.w += p.w;
            }
            xh[i][0] = pack_h2(v.x, v.y);
            xh[i][1] = pack_h2(v.z, v.w);
        }
    };

    auto store_smem = [&]() {
#pragma unroll
        for (int i = 0; i < 4; i++) {
            int f = tid + i * 256;
            int arow = f >> 3, ac4 = f & 7;
            *(uint2*)(&As[arow][ac4 * 4]) = make_uint2(ah[i][0], ah[i][1]);
            int krow = f >> 5, n4 = f & 31;
            *(uint2*)(&Xs[krow][n4 * 4]) = make_uint2(xh[i][0], xh[i][1]);
        }
    };

    auto compute = [&]() {
#pragma unroll
        for (int ks = 0; ks < 2; ks++) {
            uint32_t af[2][4];
#pragma unroll
            for (int mt = 0; mt < 2; mt++)
                ldsm_x4(af[mt][0], af[mt][1], af[mt][2], af[mt][3],
                        a_addr[mt] + ks * 32);            // +16 halves = 32 B
#pragma unroll
            for (int np = 0; np < 4; np++) {
                uint32_t b0, b1, b2, b3;
                ldsm_x4_t(b0, b1, b2, b3,
                          b_addr[np] + ks * 16 * XKH * 2); // +16 k-rows
#pragma unroll
                for (int mt = 0; mt < 2; mt++) {
                    mma_f16(acc[mt][np * 2][0], acc[mt][np * 2][1],
                            acc[mt][np * 2][2], acc[mt][np * 2][3],
                            af[mt][0], af[mt][1], af[mt][2], af[mt][3], b0, b1);
                    mma_f16(acc[mt][np * 2 + 1][0], acc[mt][np * 2 + 1][1],
                            acc[mt][np * 2 + 1][2], acc[mt][np * 2 + 1][3],
                            af[mt][0], af[mt][1], af[mt][2], af[mt][3], b2, b3);
                }
            }
        }
    };

    const int NK = K / 32;   // 16
    load_regs(0);
    store_smem();
    __syncthreads();

#pragma unroll 1
    for (int k0 = 32; k0 < K; k0 += 32) {
        load_regs(k0);       // LDG + pack overlaps compute below
        compute();
        __syncthreads();
        store_smem();
        __syncthreads();
    }
    compute();

    // ---- epilogue ----
#pragma unroll
    for (int mt = 0; mt < 2; mt++) {
        int r = tileM + m0 + mt * 16 + group;
#pragma unroll
        for (int nt = 0; nt < 8; nt++) {
            int c = tileN + n0w + nt * 8 + tig * 2;
            float2 v0, v1;
            v0.x = acc[mt][nt][0]; v0.y = acc[mt][nt][1];
            v1.x = acc[mt][nt][2]; v1.y = acc[mt][nt][3];
            if (RELU) {
                v0.x = fmaxf(v0.x, 0.0f); v0.y = fmaxf(v0.y, 0.0f);
                v1.x = fmaxf(v1.x, 0.0f); v1.y = fmaxf(v1.y, 0.0f);
            }
            *(float2*)(Cb + (size_t)r * N + c)       = v0;
            *(float2*)(Cb + (size_t)(r + 8) * N + c) = v1;
        }
    }
}

__global__ __launch_bounds__(256) void gemm_qk(
    const float* __restrict__ A, const float* __restrict__ x,
    const float* __restrict__ pos)
{
    gemm_tc_body<true, true>(A, x, pos, g_QK, 1024, CCH, NPIX);
}

__global__ __launch_bounds__(256) void gemm_v(
    const float* __restrict__ A, const float* __restrict__ x)
{
    gemm_tc_body<false, false>(A, x, nullptr, g_V, 512, CCH, NPIX);
}

__global__ __launch_bounds__(256) void gemm_o(
    const float* __restrict__ A, float* __restrict__ out)
{
    gemm_tc_body<false, false>(A, g_V, nullptr, out, 512, CCH, NPIX);
}

// ---------------------------------------------------------------------------
// KV kernel (mma.sync tf32), split 4-way over N (R11, passing).
// ---------------------------------------------------------------------------
#define KVS 68

__global__ __launch_bounds__(256) void kv_mma_kernel()
{
    const int bh = blockIdx.x;
    const int sp = blockIdx.y;
    const int b = bh >> 3, h = bh & 7;
    const float* kp = g_QK + ((size_t)b * 1024 + 512 + h * 64) * NPIX;
    const float* vp = g_V  + ((size_t)b * 512  +       h * 64) * NPIX;

    __shared__ uint32_t Vs[80][KVS];
    __shared__ uint32_t Ks[64][KVS];

    const int tid  = threadIdx.x;
    const int warp = tid >> 5;
    const int lane = tid & 31;
    const int group = lane >> 2;
    const int tig   = lane & 3;

    for (int i = tid; i < 16 * KVS; i += 256) {
        int r = 64 + i / KVS, c = i % KVS;
        Vs[r][c] = (r == 64) ? __float_as_uint(1.0f) : 0u;
    }

    float acc[5][4];
#pragma unroll
    for (int mt = 0; mt < 5; mt++)
#pragma unroll
        for (int i = 0; i < 4; i++) acc[mt][i] = 0.0f;

    const int nbeg = sp * KV_CHUNK;
    const int nend = nbeg + KV_CHUNK;
    for (int n0 = nbeg; n0 < nend; n0 += 64) {
        __syncthreads();
#pragma unroll
        for (int i = 0; i < 4; i++) {
            int f = tid + i * 256;
            int row = f >> 4, c4 = f & 15;
            float4 v = *(const float4*)(vp + (size_t)row * NPIX + n0 + c4 * 4);
            uint4 vt;
            vt.x = f2tf32(v.x); vt.y = f2tf32(v.y); vt.z = f2tf32(v.z); vt.w = f2tf32(v.w);
            *(uint4*)(&Vs[row][c4 * 4]) = vt;
            float4 kk = *(const float4*)(kp + (size_t)row * NPIX + n0 + c4 * 4);
            uint4 kt;
            kt.x = f2tf32(kk.x); kt.y = f2tf32(kk.y); kt.z = f2tf32(kk.z); kt.w = f2tf32(kk.w);
            *(uint4*)(&Ks[row][c4 * 4]) = kt;
        }
        __syncthreads();

#pragma unroll
        for (int ks = 0; ks < 8; ks++) {
            const int k = ks * 8;
            uint32_t b0 = Ks[warp * 8 + group][k + tig];
            uint32_t b1 = Ks[warp * 8 + group][k + tig + 4];
#pragma unroll
            for (int mt = 0; mt < 5; mt++) {
                int r = mt * 16 + group;
                uint32_t a0 = Vs[r    ][k + tig];
                uint32_t a1 = Vs[r + 8][k + tig];
                uint32_t a2 = Vs[r    ][k + tig + 4];
                uint32_t a3 = Vs[r + 8][k + tig + 4];
                mma_tf32(acc[mt][0], acc[mt][1], acc[mt][2], acc[mt][3],
                         a0, a1, a2, a3, b0, b1);
            }
        }
    }

    float* kvb = g_KVp + ((size_t)sp * BATCH * NHEAD + bh) * 65 * 64;
#pragma unroll
    for (int mt = 0; mt < 5; mt++) {
        int r0 = mt * 16 + group;
        int r1 = r0 + 8;
        int c = warp * 8 + tig * 2;
        if (r0 < 65) {
            kvb[r0 * 64 + c]     = acc[mt][0];
            kvb[r0 * 64 + c + 1] = acc[mt][1];
        }
        if (r1 < 65) {
            kvb[r1 * 64 + c]     = acc[mt][2];
            kvb[r1 * 64 + c + 1] = acc[mt][3];
        }
    }
}

__global__ __launch_bounds__(256) void kv_reduce_kernel()
{
    const int bh = blockIdx.x;
    const size_t stride = (size_t)BATCH * NHEAD * 65 * 64;
    float* dst = g_KV + (size_t)bh * 65 * 64;
    const float* src = g_KVp + (size_t)bh * 65 * 64;
    for (int i = threadIdx.x; i < 65 * 64; i += 256) {
        float s = src[i];
#pragma unroll
        for (int sp = 1; sp < KV_SPLIT; sp++)
            s += src[sp * stride + i];
        dst[i] = s;
    }
}

// ---------------------------------------------------------------------------
// Attention output (mma.sync tf32), unchanged from R11.
// ---------------------------------------------------------------------------
#define QS 136

__global__ __launch_bounds__(256) void attn_mma_kernel()
{
    const int bh = blockIdx.y;
    const int b = bh >> 3, h = bh & 7;
    const int ntile = blockIdx.x * 128;

    __shared__ uint32_t As[80][KVS];
    __shared__ uint32_t Qs[64][QS];
    __shared__ float norms[8][16];

    const int tid  = threadIdx.x;
    const int warp = tid >> 5;
    const int lane = tid & 31;
    const int group = lane >> 2;
    const int tig   = lane & 3;

    const float* kvb = g_KV + (size_t)bh * 65 * 64;
    for (int i = tid; i < 80 * 64; i += 256) {
        int r = i >> 6, c = i & 63;
        As[r][c] = (r < 65) ? f2tf32(kvb[i]) : 0u;
    }
    const float* q = g_QK + ((size_t)b * 1024 + h * 64) * NPIX + ntile;
#pragma unroll
    for (int i = 0; i < 8; i++) {
        int f = tid + i * 256;
        int row = f >> 5, c4 = f & 31;
        float4 v = *(const float4*)(q + (size_t)row * NPIX + c4 * 4);
        uint4 t;
        t.x = f2tf32(v.x); t.y = f2tf32(v.y); t.z = f2tf32(v.z); t.w = f2tf32(v.w);
        *(uint4*)(&Qs[row][c4 * 4]) = t;
    }
    __syncthreads();

    float acc[5][2][4];
#pragma unroll
    for (int mt = 0; mt < 5; mt++)
#pragma unroll
        for (int nt = 0; nt < 2; nt++)
#pragma unroll
            for (int i = 0; i < 4; i++) acc[mt][nt][i] = 0.0f;

#pragma unroll
    for (int ks = 0; ks < 8; ks++) {
        const int k = ks * 8;
        uint32_t bf[2][2];
#pragma unroll
        for (int nt = 0; nt < 2; nt++) {
            int c = warp * 16 + nt * 8 + group;
            bf[nt][0] = Qs[k + tig    ][c];
            bf[nt][1] = Qs[k + tig + 4][c];
        }
#pragma unroll
        for (int mt = 0; mt < 5; mt++) {
            int r = mt * 16 + group;
            uint32_t a0 = As[r    ][k + tig];
            uint32_t a1 = As[r + 8][k + tig];
            uint32_t a2 = As[r    ][k + tig + 4];
            uint32_t a3 = As[r + 8][k + tig + 4];
#pragma unroll
            for (int nt = 0; nt < 2; nt++)
                mma_tf32(acc[mt][nt][0], acc[mt][nt][1],
                         acc[mt][nt][2], acc[mt][nt][3],
                         a0, a1, a2, a3, bf[nt][0], bf[nt][1]);
        }
    }

    if (group == 0) {
#pragma unroll
        for (int nt = 0; nt < 2; nt++) {
            norms[warp][nt * 8 + tig * 2]     = acc[4][nt][0];
            norms[warp][nt * 8 + tig * 2 + 1] = acc[4][nt][1];
        }
    }
    __syncwarp();

    float* ob = g_V + ((size_t)b * 512 + h * 64) * NPIX + ntile;
#pragma unroll
    for (int nt = 0; nt < 2; nt++) {
        int cl = nt * 8 + tig * 2;
        float inv0 = 1.0f / (norms[warp][cl]     + EPS);
        float inv1 = 1.0f / (norms[warp][cl + 1] + EPS);
        int c = warp * 16 + cl;
#pragma unroll
        for (int mt = 0; mt < 4; mt++) {
            int r0 = mt * 16 + group;
            float2 v0, v1;
            v0.x = acc[mt][nt][0] * inv0; v0.y = acc[mt][nt][1] * inv1;
            v1.x = acc[mt][nt][2] * inv0; v1.y = acc[mt][nt][3] * inv1;
            *(float2*)(ob + (size_t)r0 * NPIX + c)       = v0;
            *(float2*)(ob + (size_t)(r0 + 8) * NPIX + c) = v1;
        }
    }
}

// ---------------------------------------------------------------------------
extern "C" void kernel_launch(void* const* d_in, const int* in_sizes, int n_in,
                              void* d_out, int out_size)
{
    const float* x    = (const float*)d_in[0];
    const float* pos  = (const float*)d_in[1];
    const float* w_qk = (const float*)d_in[2];
    const float* w_v  = (const float*)d_in[3];
    const float* w_o  = (const float*)d_in[4];
    float* out = (float*)d_out;

    dim3 thr(256);

    // 1) qk = relu(w_qk @ (x+pos))   [B,1024,N]
    gemm_qk<<<dim3(NPIX / 128, 1024 / 128, BATCH), thr>>>(w_qk, x, pos);

    // 2) v = w_v @ x                 [B,512,N]
    gemm_v<<<dim3(NPIX / 128, 512 / 128, BATCH), thr>>>(w_v, x);

    // 3) kv partials + reduce        [B,H,65,64]
    kv_mma_kernel<<<dim3(BATCH * NHEAD, KV_SPLIT), 256>>>();
    kv_reduce_kernel<<<BATCH * NHEAD, 256>>>();

    // 4) out = normalize(kv @ q)     [B,512,N]  in-place over g_V
    attn_mma_kernel<<<dim3(NPIX / 128, BATCH * NHEAD), 256>>>();

    // 5) final = w_o @ out           [B,512,N]
    gemm_o<<<dim3(NPIX / 128, 512 / 128, BATCH), thr>>>(w_o, out);
}

// round 14
// speedup vs baseline: 2.3726x; 1.2302x over previous
#include <cuda_runtime.h>
#include <cuda_fp16.h>
#include <cstdint>

// Problem constants
#define BATCH 16
#define CCH   512
#define NPIX  4096          // 64*64
#define NHEAD 8
#define EPS   1e-6f

#define KV_SPLIT 4
#define KV_CHUNK (NPIX / KV_SPLIT)

// Scratch (device globals - no allocation at launch time).
__device__ __half g_XH [(size_t)BATCH * CCH * NPIX];    // f16(x)
__device__ __half g_XPH[(size_t)BATCH * CCH * NPIX];    // f16(x+pos)
__device__ __half g_WQ [1024 * 512];
__device__ __half g_WV [512 * 512];
__device__ __half g_WO [512 * 512];
__device__ __half g_QK [(size_t)BATCH * 1024 * NPIX];   // fp16 q|k
__device__ __half g_V  [(size_t)BATCH * CCH  * NPIX];   // fp16 V, then attn out
__device__ float  g_KV [(size_t)BATCH * NHEAD * 65 * 64];
__device__ float  g_KVp[(size_t)KV_SPLIT * BATCH * NHEAD * 65 * 64];

// ---------------------------------------------------------------------------
// helpers
// ---------------------------------------------------------------------------
__device__ __forceinline__ uint32_t f2tf32(float f) {
    uint32_t r;
    asm("cvt.rna.tf32.f32 %0, %1;" : "=r"(r) : "f"(f));
    return r;
}

__device__ __forceinline__ void mma_tf32(
    float& c0, float& c1, float& c2, float& c3,
    uint32_t a0, uint32_t a1, uint32_t a2, uint32_t a3,
    uint32_t b0, uint32_t b1)
{
    asm volatile(
        "mma.sync.aligned.m16n8k8.row.col.f32.tf32.tf32.f32 "
        "{%0,%1,%2,%3}, {%4,%5,%6,%7}, {%8,%9}, {%0,%1,%2,%3};"
        : "+f"(c0), "+f"(c1), "+f"(c2), "+f"(c3)
        : "r"(a0), "r"(a1), "r"(a2), "r"(a3), "r"(b0), "r"(b1));
}

__device__ __forceinline__ void mma_f16(
    float& c0, float& c1, float& c2, float& c3,
    uint32_t a0, uint32_t a1, uint32_t a2, uint32_t a3,
    uint32_t b0, uint32_t b1)
{
    asm volatile(
        "mma.sync.aligned.m16n8k16.row.col.f32.f16.f16.f32 "
        "{%0,%1,%2,%3}, {%4,%5,%6,%7}, {%8,%9}, {%0,%1,%2,%3};"
        : "+f"(c0), "+f"(c1), "+f"(c2), "+f"(c3)
        : "r"(a0), "r"(a1), "r"(a2), "r"(a3), "r"(b0), "r"(b1));
}

__device__ __forceinline__ uint32_t pack_h2(float lo, float hi) {
    __half2 h = __floats2half2_rn(lo, hi);
    return *(uint32_t*)&h;
}

__device__ __forceinline__ uint32_t smem_u32(const void* p) {
    uint32_t a;
    asm("{ .reg .u64 t; cvta.to.shared.u64 t, %1; cvt.u32.u64 %0, t; }"
        : "=r"(a) : "l"(p));
    return a;
}

__device__ __forceinline__ void ldsm_x4(
    uint32_t& r0, uint32_t& r1, uint32_t& r2, uint32_t& r3, uint32_t addr)
{
    asm volatile("ldmatrix.sync.aligned.m8n8.x4.shared.b16 {%0,%1,%2,%3}, [%4];"
        : "=r"(r0), "=r"(r1), "=r"(r2), "=r"(r3) : "r"(addr));
}

__device__ __forceinline__ void ldsm_x4_t(
    uint32_t& r0, uint32_t& r1, uint32_t& r2, uint32_t& r3, uint32_t addr)
{
    asm volatile("ldmatrix.sync.aligned.m8n8.x4.trans.shared.b16 {%0,%1,%2,%3}, [%4];"
        : "=r"(r0), "=r"(r1), "=r"(r2), "=r"(r3) : "r"(addr));
}

// ---------------------------------------------------------------------------
// Pre-pass: convert inputs + weights to fp16.
// ---------------------------------------------------------------------------
__global__ __launch_bounds__(256) void cvt_x_kernel(
    const float* __restrict__ x, const float* __restrict__ pos)
{
    size_t i = ((size_t)blockIdx.x * 256 + threadIdx.x) * 8;
    float4 x0 = *(const float4*)(x + i);
    float4 x1 = *(const float4*)(x + i + 4);
    float4 p0 = *(const float4*)(pos + i);
    float4 p1 = *(const float4*)(pos + i + 4);
    uint4 h, s;
    h.x = pack_h2(x0.x, x0.y); h.y = pack_h2(x0.z, x0.w);
    h.z = pack_h2(x1.x, x1.y); h.w = pack_h2(x1.z, x1.w);
    s.x = pack_h2(x0.x + p0.x, x0.y + p0.y);
    s.y = pack_h2(x0.z + p0.z, x0.w + p0.w);
    s.z = pack_h2(x1.x + p1.x, x1.y + p1.y);
    s.w = pack_h2(x1.z + p1.z, x1.w + p1.w);
    *(uint4*)(&g_XH[i])  = h;
    *(uint4*)(&g_XPH[i]) = s;
}

__global__ __launch_bounds__(256) void cvt_w_kernel(
    const float* __restrict__ wq, const float* __restrict__ wv,
    const float* __restrict__ wo)
{
    int i = (blockIdx.x * 256 + threadIdx.x) * 4;
    if (i < 1024 * 512) {
        float4 v = *(const float4*)(wq + i);
        *(uint2*)(&g_WQ[i]) = make_uint2(pack_h2(v.x, v.y), pack_h2(v.z, v.w));
    }
    if (i < 512 * 512) {
        float4 v = *(const float4*)(wv + i);
        *(uint2*)(&g_WV[i]) = make_uint2(pack_h2(v.x, v.y), pack_h2(v.z, v.w));
        float4 w = *(const float4*)(wo + i);
        *(uint2*)(&g_WO[i]) = make_uint2(pack_h2(w.x, w.y), pack_h2(w.z, w.w));
    }
}

// ---------------------------------------------------------------------------
// All-fp16 ldmatrix GEMM: C[b](MxN) = A(MxK) * X[b](KxN), all operands fp16.
// 256 threads, 128x128x32 tiles. 8 warps (4x2); warp = 32x64 via m16n8k16.
// Fragment layouts identical to the passing R13 kernel.
// ---------------------------------------------------------------------------
#define AKH 40     // halves per A row (32 + 8 pad)
#define XKH 136    // halves per X row (128 + 8 pad)

template<bool RELU, bool OUT_HALF>
__device__ __forceinline__ void gemm_tc_body(
    const __half* __restrict__ A,
    const __half* __restrict__ X,
    void* __restrict__ Cv,
    int M, int K, int N)
{
    const int b = blockIdx.z;
    const __half* Xb = X + (size_t)b * K * N;

    const int tileM = blockIdx.y * 128;
    const int tileN = blockIdx.x * 128;

    __shared__ __half As[128][AKH];   // [m][k]
    __shared__ __half Xs[32][XKH];    // [k][n]

    const int tid   = threadIdx.x;
    const int warp  = tid >> 5;
    const int lane  = tid & 31;
    const int group = lane >> 2;
    const int tig   = lane & 3;
    const int warp_m = warp >> 1;
    const int warp_n = warp & 1;
    const int m0  = warp_m * 32;
    const int n0w = warp_n * 64;

    const int rowoff = (lane & 7) + ((lane >> 3) & 1) * 8;
    const int hioff  = (lane >= 16) ? 8 : 0;

    uint32_t a_addr[2], b_addr[4];
#pragma unroll
    for (int mt = 0; mt < 2; mt++)
        a_addr[mt] = smem_u32(&As[m0 + mt * 16 + rowoff][hioff]);
#pragma unroll
    for (int np = 0; np < 4; np++)
        b_addr[np] = smem_u32(&Xs[rowoff][n0w + np * 16 + hioff]);

    float acc[2][8][4];
#pragma unroll
    for (int mt = 0; mt < 2; mt++)
#pragma unroll
        for (int nt = 0; nt < 8; nt++)
#pragma unroll
            for (int i = 0; i < 4; i++) acc[mt][nt][i] = 0.0f;

    uint4 av[2], xv[2];    // staged fp16 tiles (next K-tile)

    auto load_regs = [&](int k0) {
#pragma unroll
        for (int i = 0; i < 2; i++) {
            int f = tid + i * 256;          // 0..511
            int arow = f >> 2, ac = f & 3;  // A: 128 rows x 4 chunks of 8 halves
            av[i] = *(const uint4*)(A + (size_t)(tileM + arow) * K + k0 + ac * 8);
            int krow = f >> 4, n16 = f & 15;  // X: 32 rows x 16 chunks of 8 halves
            xv[i] = *(const uint4*)(Xb + (size_t)(k0 + krow) * N + tileN + n16 * 8);
        }
    };

    auto store_smem = [&]() {
#pragma unroll
        for (int i = 0; i < 2; i++) {
            int f = tid + i * 256;
            int arow = f >> 2, ac = f & 3;
            *(uint4*)(&As[arow][ac * 8]) = av[i];
            int krow = f >> 4, n16 = f & 15;
            *(uint4*)(&Xs[krow][n16 * 8]) = xv[i];
        }
    };

    auto compute = [&]() {
#pragma unroll
        for (int ks = 0; ks < 2; ks++) {
            uint32_t af[2][4];
#pragma unroll
            for (int mt = 0; mt < 2; mt++)
                ldsm_x4(af[mt][0], af[mt][1], af[mt][2], af[mt][3],
                        a_addr[mt] + ks * 32);
#pragma unroll
            for (int np = 0; np < 4; np++) {
                uint32_t b0, b1, b2, b3;
                ldsm_x4_t(b0, b1, b2, b3, b_addr[np] + ks * 16 * XKH * 2);
#pragma unroll
                for (int mt = 0; mt < 2; mt++) {
                    mma_f16(acc[mt][np * 2][0], acc[mt][np * 2][1],
                            acc[mt][np * 2][2], acc[mt][np * 2][3],
                            af[mt][0], af[mt][1], af[mt][2], af[mt][3], b0, b1);
                    mma_f16(acc[mt][np * 2 + 1][0], acc[mt][np * 2 + 1][1],
                            acc[mt][np * 2 + 1][2], acc[mt][np * 2 + 1][3],
                            af[mt][0], af[mt][1], af[mt][2], af[mt][3], b2, b3);
                }
            }
        }
    };

    const int NK = K / 32;   // 16
    load_regs(0);
    store_smem();
    __syncthreads();

#pragma unroll 1
    for (int k0 = 32; k0 < K; k0 += 32) {
        load_regs(k0);
        compute();
        __syncthreads();
        store_smem();
        __syncthreads();
    }
    compute();

    // ---- epilogue ----
#pragma unroll
    for (int mt = 0; mt < 2; mt++) {
        int r = tileM + m0 + mt * 16 + group;
#pragma unroll
        for (int nt = 0; nt < 8; nt++) {
            int c = tileN + n0w + nt * 8 + tig * 2;
            float v0 = acc[mt][nt][0], v1 = acc[mt][nt][1];
            float v2 = acc[mt][nt][2], v3 = acc[mt][nt][3];
            if (RELU) {
                v0 = fmaxf(v0, 0.0f); v1 = fmaxf(v1, 0.0f);
                v2 = fmaxf(v2, 0.0f); v3 = fmaxf(v3, 0.0f);
            }
            if (OUT_HALF) {
                __half* Cb = (__half*)Cv + (size_t)b * M * N;
                *(uint32_t*)(Cb + (size_t)r * N + c)       = pack_h2(v0, v1);
                *(uint32_t*)(Cb + (size_t)(r + 8) * N + c) = pack_h2(v2, v3);
            } else {
                float* Cb = (float*)Cv + (size_t)b * M * N;
                *(float2*)(Cb + (size_t)r * N + c)       = make_float2(v0, v1);
                *(float2*)(Cb + (size_t)(r + 8) * N + c) = make_float2(v2, v3);
            }
        }
    }
}

__global__ __launch_bounds__(256) void gemm_qk()
{
    gemm_tc_body<true, true>(g_WQ, g_XPH, g_QK, 1024, CCH, NPIX);
}

__global__ __launch_bounds__(256) void gemm_v()
{
    gemm_tc_body<false, true>(g_WV, g_XH, g_V, 512, CCH, NPIX);
}

__global__ __launch_bounds__(256) void gemm_o(float* __restrict__ out)
{
    gemm_tc_body<false, false>(g_WO, g_V, out, 512, CCH, NPIX);
}

// ---------------------------------------------------------------------------
// KV kernel (mma.sync tf32), fp16 inputs, split 4-way over N.
// ---------------------------------------------------------------------------
#define KVS 68

__global__ __launch_bounds__(256) void kv_mma_kernel()
{
    const int bh = blockIdx.x;
    const int sp = blockIdx.y;
    const int b = bh >> 3, h = bh & 7;
    const __half* kp = g_QK + ((size_t)b * 1024 + 512 + h * 64) * NPIX;
    const __half* vp = g_V  + ((size_t)b * 512  +       h * 64) * NPIX;

    __shared__ uint32_t Vs[80][KVS];
    __shared__ uint32_t Ks[64][KVS];

    const int tid  = threadIdx.x;
    const int warp = tid >> 5;
    const int lane = tid & 31;
    const int group = lane >> 2;
    const int tig   = lane & 3;

    for (int i = tid; i < 16 * KVS; i += 256) {
        int r = 64 + i / KVS, c = i % KVS;
        Vs[r][c] = (r == 64) ? __float_as_uint(1.0f) : 0u;
    }

    float acc[5][4];
#pragma unroll
    for (int mt = 0; mt < 5; mt++)
#pragma unroll
        for (int i = 0; i < 4; i++) acc[mt][i] = 0.0f;

    const int nbeg = sp * KV_CHUNK;
    const int nend = nbeg + KV_CHUNK;
    for (int n0 = nbeg; n0 < nend; n0 += 64) {
        __syncthreads();
#pragma unroll
        for (int i = 0; i < 2; i++) {
            int f = tid + i * 256;            // 0..511
            int row = f >> 3, c8 = f & 7;     // 64 rows x 8 chunks of 8 halves
            uint4 rv = *(const uint4*)(vp + (size_t)row * NPIX + n0 + c8 * 8);
            __half2* hv = (__half2*)&rv;
            uint4 rk = *(const uint4*)(kp + (size_t)row * NPIX + n0 + c8 * 8);
            __half2* hk = (__half2*)&rk;
            uint4 lo, hi;
            float2 t;
            t = __half22float2(hv[0]); lo.x = f2tf32(t.x); lo.y = f2tf32(t.y);
            t = __half22float2(hv[1]); lo.z = f2tf32(t.x); lo.w = f2tf32(t.y);
            t = __half22float2(hv[2]); hi.x = f2tf32(t.x); hi.y = f2tf32(t.y);
            t = __half22float2(hv[3]); hi.z = f2tf32(t.x); hi.w = f2tf32(t.y);
            *(uint4*)(&Vs[row][c8 * 8])     = lo;
            *(uint4*)(&Vs[row][c8 * 8 + 4]) = hi;
            t = __half22float2(hk[0]); lo.x = f2tf32(t.x); lo.y = f2tf32(t.y);
            t = __half22float2(hk[1]); lo.z = f2tf32(t.x); lo.w = f2tf32(t.y);
            t = __half22float2(hk[2]); hi.x = f2tf32(t.x); hi.y = f2tf32(t.y);
            t = __half22float2(hk[3]); hi.z = f2tf32(t.x); hi.w = f2tf32(t.y);
            *(uint4*)(&Ks[row][c8 * 8])     = lo;
            *(uint4*)(&Ks[row][c8 * 8 + 4]) = hi;
        }
        __syncthreads();

#pragma unroll
        for (int ks = 0; ks < 8; ks++) {
            const int k = ks * 8;
            uint32_t b0 = Ks[warp * 8 + group][k + tig];
            uint32_t b1 = Ks[warp * 8 + group][k + tig + 4];
#pragma unroll
            for (int mt = 0; mt < 5; mt++) {
                int r = mt * 16 + group;
                uint32_t a0 = Vs[r    ][k + tig];
                uint32_t a1 = Vs[r + 8][k + tig];
                uint32_t a2 = Vs[r    ][k + tig + 4];
                uint32_t a3 = Vs[r + 8][k + tig + 4];
                mma_tf32(acc[mt][0], acc[mt][1], acc[mt][2], acc[mt][3],
                         a0, a1, a2, a3, b0, b1);
            }
        }
    }

    float* kvb = g_KVp + ((size_t)sp * BATCH * NHEAD + bh) * 65 * 64;
#pragma unroll
    for (int mt = 0; mt < 5; mt++) {
        int r0 = mt * 16 + group;
        int r1 = r0 + 8;
        int c = warp * 8 + tig * 2;
        if (r0 < 65) {
            kvb[r0 * 64 + c]     = acc[mt][0];
            kvb[r0 * 64 + c + 1] = acc[mt][1];
        }
        if (r1 < 65) {
            kvb[r1 * 64 + c]     = acc[mt][2];
            kvb[r1 * 64 + c + 1] = acc[mt][3];
        }
    }
}

__global__ __launch_bounds__(256) void kv_reduce_kernel()
{
    const int bh = blockIdx.x;
    const size_t stride = (size_t)BATCH * NHEAD * 65 * 64;
    float* dst = g_KV + (size_t)bh * 65 * 64;
    const float* src = g_KVp + (size_t)bh * 65 * 64;
    for (int i = threadIdx.x; i < 65 * 64; i += 256) {
        float s = src[i];
#pragma unroll
        for (int sp = 1; sp < KV_SPLIT; sp++)
            s += src[sp * stride + i];
        dst[i] = s;
    }
}

// ---------------------------------------------------------------------------
// Attention output (mma.sync tf32), fp16 q input, fp16 output into g_V.
// ---------------------------------------------------------------------------
#define QS 136

__global__ __launch_bounds__(256) void attn_mma_kernel()
{
    const int bh = blockIdx.y;
    const int b = bh >> 3, h = bh & 7;
    const int ntile = blockIdx.x * 128;

    __shared__ uint32_t As[80][KVS];
    __shared__ uint32_t Qs[64][QS];
    __shared__ float norms[8][16];

    const int tid  = threadIdx.x;
    const int warp = tid >> 5;
    const int lane = tid & 31;
    const int group = lane >> 2;
    const int tig   = lane & 3;

    const float* kvb = g_KV + (size_t)bh * 65 * 64;
    for (int i = tid; i < 80 * 64; i += 256) {
        int r = i >> 6, c = i & 63;
        As[r][c] = (r < 65) ? f2tf32(kvb[i]) : 0u;
    }
    const __half* q = g_QK + ((size_t)b * 1024 + h * 64) * NPIX + ntile;
#pragma unroll
    for (int i = 0; i < 4; i++) {
        int f = tid + i * 256;                // 0..1023
        int row = f >> 4, c8 = f & 15;        // 64 rows x 16 chunks of 8 halves
        uint4 raw = *(const uint4*)(q + (size_t)row * NPIX + c8 * 8);
        __half2* hh = (__half2*)&raw;
        uint4 lo, hi;
        float2 t;
        t = __half22float2(hh[0]); lo.x = f2tf32(t.x); lo.y = f2tf32(t.y);
        t = __half22float2(hh[1]); lo.z = f2tf32(t.x); lo.w = f2tf32(t.y);
        t = __half22float2(hh[2]); hi.x = f2tf32(t.x); hi.y = f2tf32(t.y);
        t = __half22float2(hh[3]); hi.z = f2tf32(t.x); hi.w = f2tf32(t.y);
        *(uint4*)(&Qs[row][c8 * 8])     = lo;
        *(uint4*)(&Qs[row][c8 * 8 + 4]) = hi;
    }
    __syncthreads();

    float acc[5][2][4];
#pragma unroll
    for (int mt = 0; mt < 5; mt++)
#pragma unroll
        for (int nt = 0; nt < 2; nt++)
#pragma unroll
            for (int i = 0; i < 4; i++) acc[mt][nt][i] = 0.0f;

#pragma unroll
    for (int ks = 0; ks < 8; ks++) {
        const int k = ks * 8;
        uint32_t bf[2][2];
#pragma unroll
        for (int nt = 0; nt < 2; nt++) {
            int c = warp * 16 + nt * 8 + group;
            bf[nt][0] = Qs[k + tig    ][c];
            bf[nt][1] = Qs[k + tig + 4][c];
        }
#pragma unroll
        for (int mt = 0; mt < 5; mt++) {
            int r = mt * 16 + group;
            uint32_t a0 = As[r    ][k + tig];
            uint32_t a1 = As[r + 8][k + tig];
            uint32_t a2 = As[r    ][k + tig + 4];
            uint32_t a3 = As[r + 8][k + tig + 4];
#pragma unroll
            for (int nt = 0; nt < 2; nt++)
                mma_tf32(acc[mt][nt][0], acc[mt][nt][1],
                         acc[mt][nt][2], acc[mt][nt][3],
                         a0, a1, a2, a3, bf[nt][0], bf[nt][1]);
        }
    }

    if (group == 0) {
#pragma unroll
        for (int nt = 0; nt < 2; nt++) {
            norms[warp][nt * 8 + tig * 2]     = acc[4][nt][0];
            norms[warp][nt * 8 + tig * 2 + 1] = acc[4][nt][1];
        }
    }
    __syncwarp();

    __half* ob = g_V + ((size_t)b * 512 + h * 64) * NPIX + ntile;
#pragma unroll
    for (int nt = 0; nt < 2; nt++) {
        int cl = nt * 8 + tig * 2;
        float inv0 = 1.0f / (norms[warp][cl]     + EPS);
        float inv1 = 1.0f / (norms[warp][cl + 1] + EPS);
        int c = warp * 16 + cl;
#pragma unroll
        for (int mt = 0; mt < 4; mt++) {
            int r0 = mt * 16 + group;
            *(uint32_t*)(ob + (size_t)r0 * NPIX + c) =
                pack_h2(acc[mt][nt][0] * inv0, acc[mt][nt][1] * inv1);
            *(uint32_t*)(ob + (size_t)(r0 + 8) * NPIX + c) =
                pack_h2(acc[mt][nt][2] * inv0, acc[mt][nt][3] * inv1);
        }
    }
}

// ---------------------------------------------------------------------------
extern "C" void kernel_launch(void* const* d_in, const int* in_sizes, int n_in,
                              void* d_out, int out_size)
{
    const float* x    = (const float*)d_in[0];
    const float* pos  = (const float*)d_in[1];
    const float* w_qk = (const float*)d_in[2];
    const float* w_v  = (const float*)d_in[3];
    const float* w_o  = (const float*)d_in[4];
    float* out = (float*)d_out;

    dim3 thr(256);

    // 0) fp16 pre-pass
    cvt_w_kernel<<<512, thr>>>(w_qk, w_v, w_o);
    cvt_x_kernel<<<(int)(((size_t)BATCH * CCH * NPIX) / 8 / 256), thr>>>(x, pos);

    // 1) qk = relu(Wqk @ f16(x+pos))   [B,1024,N] fp16
    gemm_qk<<<dim3(NPIX / 128, 1024 / 128, BATCH), thr>>>();

    // 2) v = Wv @ f16(x)               [B,512,N] fp16
    gemm_v<<<dim3(NPIX / 128, 512 / 128, BATCH), thr>>>();

    // 3) kv partials + reduce          [B,H,65,64] f32
    kv_mma_kernel<<<dim3(BATCH * NHEAD, KV_SPLIT), 256>>>();
    kv_reduce_kernel<<<BATCH * NHEAD, 256>>>();

    // 4) out = normalize(kv @ q)       [B,512,N] fp16, in-place over g_V
    attn_mma_kernel<<<dim3(NPIX / 128, BATCH * NHEAD), 256>>>();

    // 5) final = Wo @ out              [B,512,N] f32 -> d_out
    gemm_o<<<dim3(NPIX / 128, 512 / 128, BATCH), thr>>>(out);
}

// round 15
// speedup vs baseline: 2.5320x; 1.0672x over previous
#include <cuda_runtime.h>
#include <cuda_fp16.h>
#include <cstdint>

// Problem constants
#define BATCH 16
#define CCH   512
#define NPIX  4096          // 64*64
#define NHEAD 8
#define EPS   1e-6f

#define KV_SPLIT 4
#define KV_CHUNK (NPIX / KV_SPLIT)

// Scratch (device globals - no allocation at launch time).
__device__ __half g_XH [(size_t)BATCH * CCH * NPIX];    // f16(x)
__device__ __half g_XPH[(size_t)BATCH * CCH * NPIX];    // f16(x+pos)
__device__ __half g_WQ [1024 * 512];
__device__ __half g_WV [512 * 512];
__device__ __half g_WO [512 * 512];
__device__ __half g_QK [(size_t)BATCH * 1024 * NPIX];   // fp16 q|k
__device__ __half g_V  [(size_t)BATCH * CCH  * NPIX];   // fp16 V, then attn out
__device__ float  g_KV [(size_t)BATCH * NHEAD * 65 * 64];
__device__ float  g_KVp[(size_t)KV_SPLIT * BATCH * NHEAD * 65 * 64];

// ---------------------------------------------------------------------------
// helpers
// ---------------------------------------------------------------------------
__device__ __forceinline__ uint32_t f2tf32(float f) {
    uint32_t r;
    asm("cvt.rna.tf32.f32 %0, %1;" : "=r"(r) : "f"(f));
    return r;
}

__device__ __forceinline__ void mma_tf32(
    float& c0, float& c1, float& c2, float& c3,
    uint32_t a0, uint32_t a1, uint32_t a2, uint32_t a3,
    uint32_t b0, uint32_t b1)
{
    asm volatile(
        "mma.sync.aligned.m16n8k8.row.col.f32.tf32.tf32.f32 "
        "{%0,%1,%2,%3}, {%4,%5,%6,%7}, {%8,%9}, {%0,%1,%2,%3};"
        : "+f"(c0), "+f"(c1), "+f"(c2), "+f"(c3)
        : "r"(a0), "r"(a1), "r"(a2), "r"(a3), "r"(b0), "r"(b1));
}

__device__ __forceinline__ void mma_f16(
    float& c0, float& c1, float& c2, float& c3,
    uint32_t a0, uint32_t a1, uint32_t a2, uint32_t a3,
    uint32_t b0, uint32_t b1)
{
    asm volatile(
        "mma.sync.aligned.m16n8k16.row.col.f32.f16.f16.f32 "
        "{%0,%1,%2,%3}, {%4,%5,%6,%7}, {%8,%9}, {%0,%1,%2,%3};"
        : "+f"(c0), "+f"(c1), "+f"(c2), "+f"(c3)
        : "r"(a0), "r"(a1), "r"(a2), "r"(a3), "r"(b0), "r"(b1));
}

__device__ __forceinline__ uint32_t pack_h2(float lo, float hi) {
    __half2 h = __floats2half2_rn(lo, hi);
    return *(uint32_t*)&h;
}

__device__ __forceinline__ uint32_t smem_u32(const void* p) {
    uint32_t a;
    asm("{ .reg .u64 t; cvta.to.shared.u64 t, %1; cvt.u32.u64 %0, t; }"
        : "=r"(a) : "l"(p));
    return a;
}

__device__ __forceinline__ void ldsm_x4(
    uint32_t& r0, uint32_t& r1, uint32_t& r2, uint32_t& r3, uint32_t addr)
{
    asm volatile("ldmatrix.sync.aligned.m8n8.x4.shared.b16 {%0,%1,%2,%3}, [%4];"
        : "=r"(r0), "=r"(r1), "=r"(r2), "=r"(r3) : "r"(addr));
}

__device__ __forceinline__ void ldsm_x4_t(
    uint32_t& r0, uint32_t& r1, uint32_t& r2, uint32_t& r3, uint32_t addr)
{
    asm volatile("ldmatrix.sync.aligned.m8n8.x4.trans.shared.b16 {%0,%1,%2,%3}, [%4];"
        : "=r"(r0), "=r"(r1), "=r"(r2), "=r"(r3) : "r"(addr));
}

// ---------------------------------------------------------------------------
// Pre-pass: convert inputs + weights to fp16.
// ---------------------------------------------------------------------------
__global__ __launch_bounds__(256) void cvt_x_kernel(
    const float* __restrict__ x, const float* __restrict__ pos)
{
    size_t i = ((size_t)blockIdx.x * 256 + threadIdx.x) * 8;
    float4 x0 = *(const float4*)(x + i);
    float4 x1 = *(const float4*)(x + i + 4);
    float4 p0 = *(const float4*)(pos + i);
    float4 p1 = *(const float4*)(pos + i + 4);
    uint4 h, s;
    h.x = pack_h2(x0.x, x0.y); h.y = pack_h2(x0.z, x0.w);
    h.z = pack_h2(x1.x, x1.y); h.w = pack_h2(x1.z, x1.w);
    s.x = pack_h2(x0.x + p0.x, x0.y + p0.y);
    s.y = pack_h2(x0.z + p0.z, x0.w + p0.w);
    s.z = pack_h2(x1.x + p1.x, x1.y + p1.y);
    s.w = pack_h2(x1.z + p1.z, x1.w + p1.w);
    *(uint4*)(&g_XH[i])  = h;
    *(uint4*)(&g_XPH[i]) = s;
}

__global__ __launch_bounds__(256) void cvt_w_kernel(
    const float* __restrict__ wq, const float* __restrict__ wv,
    const float* __restrict__ wo)
{
    int i = (blockIdx.x * 256 + threadIdx.x) * 4;
    if (i < 1024 * 512) {
        float4 v = *(const float4*)(wq + i);
        *(uint2*)(&g_WQ[i]) = make_uint2(pack_h2(v.x, v.y), pack_h2(v.z, v.w));
    }
    if (i < 512 * 512) {
        float4 v = *(const float4*)(wv + i);
        *(uint2*)(&g_WV[i]) = make_uint2(pack_h2(v.x, v.y), pack_h2(v.z, v.w));
        float4 w = *(const float4*)(wo + i);
        *(uint2*)(&g_WO[i]) = make_uint2(pack_h2(w.x, w.y), pack_h2(w.z, w.w));
    }
}

// ---------------------------------------------------------------------------
// All-fp16 ldmatrix GEMM: C[b](MxN) = A(MxK) * X[b](KxN), all operands fp16.
// 128 threads (4 warps, 2x2 grid); warp computes 64x64 via m16n8k16.
// CTA tile 128x128x32. Smem traffic per K-tile: A x2 + B x2 + writes = 48KB
// (was 64KB with 8 warps) -- targets the measured L1=78.5% bottleneck.
// ---------------------------------------------------------------------------
#define AKH 40     // halves per A row (32 + 8 pad)
#define XKH 136    // halves per X row (128 + 8 pad)

template<bool RELU, bool OUT_HALF>
__device__ __forceinline__ void gemm_tc_body(
    const __half* __restrict__ A,
    const __half* __restrict__ X,
    void* __restrict__ Cv,
    int M, int K, int N)
{
    const int b = blockIdx.z;
    const __half* Xb = X + (size_t)b * K * N;

    const int tileM = blockIdx.y * 128;
    const int tileN = blockIdx.x * 128;

    __shared__ __half As[128][AKH];   // [m][k]
    __shared__ __half Xs[32][XKH];    // [k][n]

    const int tid   = threadIdx.x;
    const int warp  = tid >> 5;
    const int lane  = tid & 31;
    const int group = lane >> 2;
    const int tig   = lane & 3;
    const int warp_m = warp >> 1;          // 0..1
    const int warp_n = warp & 1;           // 0..1
    const int m0  = warp_m * 64;
    const int n0w = warp_n * 64;

    const int rowoff = (lane & 7) + ((lane >> 3) & 1) * 8;
    const int hioff  = (lane >= 16) ? 8 : 0;

    uint32_t a_addr[4], b_addr[4];
#pragma unroll
    for (int mt = 0; mt < 4; mt++)
        a_addr[mt] = smem_u32(&As[m0 + mt * 16 + rowoff][hioff]);
#pragma unroll
    for (int np = 0; np < 4; np++)
        b_addr[np] = smem_u32(&Xs[rowoff][n0w + np * 16 + hioff]);

    float acc[4][8][4];
#pragma unroll
    for (int mt = 0; mt < 4; mt++)
#pragma unroll
        for (int nt = 0; nt < 8; nt++)
#pragma unroll
            for (int i = 0; i < 4; i++) acc[mt][nt][i] = 0.0f;

    uint4 av[4], xv[4];    // staged fp16 tiles (next K-tile)

    auto load_regs = [&](int k0) {
#pragma unroll
        for (int i = 0; i < 4; i++) {
            int f = tid + i * 128;          // 0..511
            int arow = f >> 2, ac = f & 3;  // A: 128 rows x 4 chunks of 8 halves
            av[i] = *(const uint4*)(A + (size_t)(tileM + arow) * K + k0 + ac * 8);
            int krow = f >> 4, n16 = f & 15;  // X: 32 rows x 16 chunks of 8 halves
            xv[i] = *(const uint4*)(Xb + (size_t)(k0 + krow) * N + tileN + n16 * 8);
        }
    };

    auto store_smem = [&]() {
#pragma unroll
        for (int i = 0; i < 4; i++) {
            int f = tid + i * 128;
            int arow = f >> 2, ac = f & 3;
            *(uint4*)(&As[arow][ac * 8]) = av[i];
            int krow = f >> 4, n16 = f & 15;
            *(uint4*)(&Xs[krow][n16 * 8]) = xv[i];
        }
    };

    auto compute = [&]() {
#pragma unroll
        for (int ks = 0; ks < 2; ks++) {
            uint32_t af[4][4];
#pragma unroll
            for (int mt = 0; mt < 4; mt++)
                ldsm_x4(af[mt][0], af[mt][1], af[mt][2], af[mt][3],
                        a_addr[mt] + ks * 32);
#pragma unroll
            for (int np = 0; np < 4; np++) {
                uint32_t b0, b1, b2, b3;
                ldsm_x4_t(b0, b1, b2, b3, b_addr[np] + ks * 16 * XKH * 2);
#pragma unroll
                for (int mt = 0; mt < 4; mt++) {
                    mma_f16(acc[mt][np * 2][0], acc[mt][np * 2][1],
                            acc[mt][np * 2][2], acc[mt][np * 2][3],
                            af[mt][0], af[mt][1], af[mt][2], af[mt][3], b0, b1);
                    mma_f16(acc[mt][np * 2 + 1][0], acc[mt][np * 2 + 1][1],
                            acc[mt][np * 2 + 1][2], acc[mt][np * 2 + 1][3],
                            af[mt][0], af[mt][1], af[mt][2], af[mt][3], b2, b3);
                }
            }
        }
    };

    load_regs(0);
    store_smem();
    __syncthreads();

#pragma unroll 1
    for (int k0 = 32; k0 < K; k0 += 32) {
        load_regs(k0);
        compute();
        __syncthreads();
        store_smem();
        __syncthreads();
    }
    compute();

    // ---- epilogue ----
#pragma unroll
    for (int mt = 0; mt < 4; mt++) {
        int r = tileM + m0 + mt * 16 + group;
#pragma unroll
        for (int nt = 0; nt < 8; nt++) {
            int c = tileN + n0w + nt * 8 + tig * 2;
            float v0 = acc[mt][nt][0], v1 = acc[mt][nt][1];
            float v2 = acc[mt][nt][2], v3 = acc[mt][nt][3];
            if (RELU) {
                v0 = fmaxf(v0, 0.0f); v1 = fmaxf(v1, 0.0f);
                v2 = fmaxf(v2, 0.0f); v3 = fmaxf(v3, 0.0f);
            }
            if (OUT_HALF) {
                __half* Cb = (__half*)Cv + (size_t)b * M * N;
                *(uint32_t*)(Cb + (size_t)r * N + c)       = pack_h2(v0, v1);
                *(uint32_t*)(Cb + (size_t)(r + 8) * N + c) = pack_h2(v2, v3);
            } else {
                float* Cb = (float*)Cv + (size_t)b * M * N;
                *(float2*)(Cb + (size_t)r * N + c)       = make_float2(v0, v1);
                *(float2*)(Cb + (size_t)(r + 8) * N + c) = make_float2(v2, v3);
            }
        }
    }
}

__global__ __launch_bounds__(128) void gemm_qk()
{
    gemm_tc_body<true, true>(g_WQ, g_XPH, g_QK, 1024, CCH, NPIX);
}

__global__ __launch_bounds__(128) void gemm_v()
{
    gemm_tc_body<false, true>(g_WV, g_XH, g_V, 512, CCH, NPIX);
}

__global__ __launch_bounds__(128) void gemm_o(float* __restrict__ out)
{
    gemm_tc_body<false, false>(g_WO, g_V, out, 512, CCH, NPIX);
}

// ---------------------------------------------------------------------------
// KV kernel (mma.sync tf32), fp16 inputs, split 4-way over N (R14, passing).
// ---------------------------------------------------------------------------
#define KVS 68

__global__ __launch_bounds__(256) void kv_mma_kernel()
{
    const int bh = blockIdx.x;
    const int sp = blockIdx.y;
    const int b = bh >> 3, h = bh & 7;
    const __half* kp = g_QK + ((size_t)b * 1024 + 512 + h * 64) * NPIX;
    const __half* vp = g_V  + ((size_t)b * 512  +       h * 64) * NPIX;

    __shared__ uint32_t Vs[80][KVS];
    __shared__ uint32_t Ks[64][KVS];

    const int tid  = threadIdx.x;
    const int warp = tid >> 5;
    const int lane = tid & 31;
    const int group = lane >> 2;
    const int tig   = lane & 3;

    for (int i = tid; i < 16 * KVS; i += 256) {
        int r = 64 + i / KVS, c = i % KVS;
        Vs[r][c] = (r == 64) ? __float_as_uint(1.0f) : 0u;
    }

    float acc[5][4];
#pragma unroll
    for (int mt = 0; mt < 5; mt++)
#pragma unroll
        for (int i = 0; i < 4; i++) acc[mt][i] = 0.0f;

    const int nbeg = sp * KV_CHUNK;
    const int nend = nbeg + KV_CHUNK;
    for (int n0 = nbeg; n0 < nend; n0 += 64) {
        __syncthreads();
#pragma unroll
        for (int i = 0; i < 2; i++) {
            int f = tid + i * 256;            // 0..511
            int row = f >> 3, c8 = f & 7;     // 64 rows x 8 chunks of 8 halves
            uint4 rv = *(const uint4*)(vp + (size_t)row * NPIX + n0 + c8 * 8);
            __half2* hv = (__half2*)&rv;
            uint4 rk = *(const uint4*)(kp + (size_t)row * NPIX + n0 + c8 * 8);
            __half2* hk = (__half2*)&rk;
            uint4 lo, hi;
            float2 t;
            t = __half22float2(hv[0]); lo.x = f2tf32(t.x); lo.y = f2tf32(t.y);
            t = __half22float2(hv[1]); lo.z = f2tf32(t.x); lo.w = f2tf32(t.y);
            t = __half22float2(hv[2]); hi.x = f2tf32(t.x); hi.y = f2tf32(t.y);
            t = __half22float2(hv[3]); hi.z = f2tf32(t.x); hi.w = f2tf32(t.y);
            *(uint4*)(&Vs[row][c8 * 8])     = lo;
            *(uint4*)(&Vs[row][c8 * 8 + 4]) = hi;
            t = __half22float2(hk[0]); lo.x = f2tf32(t.x); lo.y = f2tf32(t.y);
            t = __half22float2(hk[1]); lo.z = f2tf32(t.x); lo.w = f2tf32(t.y);
            t = __half22float2(hk[2]); hi.x = f2tf32(t.x); hi.y = f2tf32(t.y);
            t = __half22float2(hk[3]); hi.z = f2tf32(t.x); hi.w = f2tf32(t.y);
            *(uint4*)(&Ks[row][c8 * 8])     = lo;
            *(uint4*)(&Ks[row][c8 * 8 + 4]) = hi;
        }
        __syncthreads();

#pragma unroll
        for (int ks = 0; ks < 8; ks++) {
            const int k = ks * 8;
            uint32_t b0 = Ks[warp * 8 + group][k + tig];
            uint32_t b1 = Ks[warp * 8 + group][k + tig + 4];
#pragma unroll
            for (int mt = 0; mt < 5; mt++) {
                int r = mt * 16 + group;
                uint32_t a0 = Vs[r    ][k + tig];
                uint32_t a1 = Vs[r + 8][k + tig];
                uint32_t a2 = Vs[r    ][k + tig + 4];
                uint32_t a3 = Vs[r + 8][k + tig + 4];
                mma_tf32(acc[mt][0], acc[mt][1], acc[mt][2], acc[mt][3],
                         a0, a1, a2, a3, b0, b1);
            }
        }
    }

    float* kvb = g_KVp + ((size_t)sp * BATCH * NHEAD + bh) * 65 * 64;
#pragma unroll
    for (int mt = 0; mt < 5; mt++) {
        int r0 = mt * 16 + group;
        int r1 = r0 + 8;
        int c = warp * 8 + tig * 2;
        if (r0 < 65) {
            kvb[r0 * 64 + c]     = acc[mt][0];
            kvb[r0 * 64 + c + 1] = acc[mt][1];
        }
        if (r1 < 65) {
            kvb[r1 * 64 + c]     = acc[mt][2];
            kvb[r1 * 64 + c + 1] = acc[mt][3];
        }
    }
}

__global__ __launch_bounds__(256) void kv_reduce_kernel()
{
    const int bh = blockIdx.x;
    const size_t stride = (size_t)BATCH * NHEAD * 65 * 64;
    float* dst = g_KV + (size_t)bh * 65 * 64;
    const float* src = g_KVp + (size_t)bh * 65 * 64;
    for (int i = threadIdx.x; i < 65 * 64; i += 256) {
        float s = src[i];
#pragma unroll
        for (int sp = 1; sp < KV_SPLIT; sp++)
            s += src[sp * stride + i];
        dst[i] = s;
    }
}

// ---------------------------------------------------------------------------
// Attention output (mma.sync tf32), fp16 q input, fp16 output into g_V.
// ---------------------------------------------------------------------------
#define QS 136

__global__ __launch_bounds__(256) void attn_mma_kernel()
{
    const int bh = blockIdx.y;
    const int b = bh >> 3, h = bh & 7;
    const int ntile = blockIdx.x * 128;

    __shared__ uint32_t As[80][KVS];
    __shared__ uint32_t Qs[64][QS];
    __shared__ float norms[8][16];

    const int tid  = threadIdx.x;
    const int warp = tid >> 5;
    const int lane = tid & 31;
    const int group = lane >> 2;
    const int tig   = lane & 3;

    const float* kvb = g_KV + (size_t)bh * 65 * 64;
    for (int i = tid; i < 80 * 64; i += 256) {
        int r = i >> 6, c = i & 63;
        As[r][c] = (r < 65) ? f2tf32(kvb[i]) : 0u;
    }
    const __half* q = g_QK + ((size_t)b * 1024 + h * 64) * NPIX + ntile;
#pragma unroll
    for (int i = 0; i < 4; i++) {
        int f = tid + i * 256;                // 0..1023
        int row = f >> 4, c8 = f & 15;        // 64 rows x 16 chunks of 8 halves
        uint4 raw = *(const uint4*)(q + (size_t)row * NPIX + c8 * 8);
        __half2* hh = (__half2*)&raw;
        uint4 lo, hi;
        float2 t;
        t = __half22float2(hh[0]); lo.x = f2tf32(t.x); lo.y = f2tf32(t.y);
        t = __half22float2(hh[1]); lo.z = f2tf32(t.x); lo.w = f2tf32(t.y);
        t = __half22float2(hh[2]); hi.x = f2tf32(t.x); hi.y = f2tf32(t.y);
        t = __half22float2(hh[3]); hi.z = f2tf32(t.x); hi.w = f2tf32(t.y);
        *(uint4*)(&Qs[row][c8 * 8])     = lo;
        *(uint4*)(&Qs[row][c8 * 8 + 4]) = hi;
    }
    __syncthreads();

    float acc[5][2][4];
#pragma unroll
    for (int mt = 0; mt < 5; mt++)
#pragma unroll
        for (int nt = 0; nt < 2; nt++)
#pragma unroll
            for (int i = 0; i < 4; i++) acc[mt][nt][i] = 0.0f;

#pragma unroll
    for (int ks = 0; ks < 8; ks++) {
        const int k = ks * 8;
        uint32_t bf[2][2];
#pragma unroll
        for (int nt = 0; nt < 2; nt++) {
            int c = warp * 16 + nt * 8 + group;
            bf[nt][0] = Qs[k + tig    ][c];
            bf[nt][1] = Qs[k + tig + 4][c];
        }
#pragma unroll
        for (int mt = 0; mt < 5; mt++) {
            int r = mt * 16 + group;
            uint32_t a0 = As[r    ][k + tig];
            uint32_t a1 = As[r + 8][k + tig];
            uint32_t a2 = As[r    ][k + tig + 4];
            uint32_t a3 = As[r + 8][k + tig + 4];
#pragma unroll
            for (int nt = 0; nt < 2; nt++)
                mma_tf32(acc[mt][nt][0], acc[mt][nt][1],
                         acc[mt][nt][2], acc[mt][nt][3],
                         a0, a1, a2, a3, bf[nt][0], bf[nt][1]);
        }
    }

    if (group == 0) {
#pragma unroll
        for (int nt = 0; nt < 2; nt++) {
            norms[warp][nt * 8 + tig * 2]     = acc[4][nt][0];
            norms[warp][nt * 8 + tig * 2 + 1] = acc[4][nt][1];
        }
    }
    __syncwarp();

    __half* ob = g_V + ((size_t)b * 512 + h * 64) * NPIX + ntile;
#pragma unroll
    for (int nt = 0; nt < 2; nt++) {
        int cl = nt * 8 + tig * 2;
        float inv0 = 1.0f / (norms[warp][cl]     + EPS);
        float inv1 = 1.0f / (norms[warp][cl + 1] + EPS);
        int c = warp * 16 + cl;
#pragma unroll
        for (int mt = 0; mt < 4; mt++) {
            int r0 = mt * 16 + group;
            *(uint32_t*)(ob + (size_t)r0 * NPIX + c) =
                pack_h2(acc[mt][nt][0] * inv0, acc[mt][nt][1] * inv1);
            *(uint32_t*)(ob + (size_t)(r0 + 8) * NPIX + c) =
                pack_h2(acc[mt][nt][2] * inv0, acc[mt][nt][3] * inv1);
        }
    }
}

// ---------------------------------------------------------------------------
extern "C" void kernel_launch(void* const* d_in, const int* in_sizes, int n_in,
                              void* d_out, int out_size)
{
    const float* x    = (const float*)d_in[0];
    const float* pos  = (const float*)d_in[1];
    const float* w_qk = (const float*)d_in[2];
    const float* w_v  = (const float*)d_in[3];
    const float* w_o  = (const float*)d_in[4];
    float* out = (float*)d_out;

    // 0) fp16 pre-pass
    cvt_w_kernel<<<512, 256>>>(w_qk, w_v, w_o);
    cvt_x_kernel<<<(int)(((size_t)BATCH * CCH * NPIX) / 8 / 256), 256>>>(x, pos);

    // 1) qk = relu(Wqk @ f16(x+pos))   [B,1024,N] fp16
    gemm_qk<<<dim3(NPIX / 128, 1024 / 128, BATCH), 128>>>();

    // 2) v = Wv @ f16(x)               [B,512,N] fp16
    gemm_v<<<dim3(NPIX / 128, 512 / 128, BATCH), 128>>>();

    // 3) kv partials + reduce          [B,H,65,64] f32
    kv_mma_kernel<<<dim3(BATCH * NHEAD, KV_SPLIT), 256>>>();
    kv_reduce_kernel<<<BATCH * NHEAD, 256>>>();

    // 4) out = normalize(kv @ q)       [B,512,N] fp16, in-place over g_V
    attn_mma_kernel<<<dim3(NPIX / 128, BATCH * NHEAD), 256>>>();

    // 5) final = Wo @ out              [B,512,N] f32 -> d_out
    gemm_o<<<dim3(NPIX / 128, 512 / 128, BATCH), 128>>>(out);
}